// round 14
// baseline (speedup 1.0000x reference)
#include <cuda_runtime.h>
#include <cuda_fp16.h>
#include <math.h>
#include <float.h>
#include <stdint.h>

#define B_SZ 256
#define D0 50176
#define D1 1024
#define D2 128
#define BM 128
#define BN 128
#define BK 64               // K fp16 elements per tile (128B rows)

#define NT_BS 256
#define NT_WS 512           // 8 consumer warps + 8 producer warps
#define STAGES 5

// layer0 (both warp-spec): base 28 slabs x 28 kt; poly 64 slabs x 49 kt
#define S1 28
#define KT1 28
#define S2 64
#define KT2 49
#define S0_TOT (S1 + S2)    // 92
// layer1 (bulk-sync)
#define S3 8
#define KT3 2
#define S4 16
#define KT4 4
#define SL1_TOT (S3 + S4)

#define TILE_BYTES 16384
#define SMEM_BS (4 * TILE_BYTES)
#define STAGE_BYTES (2 * TILE_BYTES)
#define SOFF_TILE 1024
#define SMEM_WS (SOFF_TILE + STAGES * STAGE_BYTES)  // 164864

__device__ float    g_part0[(size_t)S0_TOT * B_SZ * D1];
__device__ float    g_part1[(size_t)SL1_TOT * B_SZ * D2];
__device__ float    g_h0[B_SZ * D1];
__device__ unsigned g_mm[4];

__device__ __forceinline__ unsigned encf(float f) {
    unsigned u = __float_as_uint(f);
    return (u & 0x80000000u) ? ~u : (u | 0x80000000u);
}
__device__ __forceinline__ float decf(unsigned u) {
    u = (u & 0x80000000u) ? (u & 0x7FFFFFFFu) : ~u;
    return __uint_as_float(u);
}
__device__ __forceinline__ uint32_t pack2(float a, float b) {
    __half2 h = __floats2half2_rn(a, b);
    return *reinterpret_cast<uint32_t*>(&h);
}
__device__ __forceinline__ float silu(float a) {
    return __fdividef(a, 1.0f + __expf(-a));
}
__device__ __forceinline__ uint32_t smem_u32(const void* p) {
    uint32_t a;
    asm("{ .reg .u64 t; cvta.to.shared.u64 t, %1; cvt.u32.u64 %0, t; }" : "=r"(a) : "l"(p));
    return a;
}
__device__ __forceinline__ void mbar_init(uint32_t m, uint32_t cnt) {
    asm volatile("mbarrier.init.shared.b64 [%0], %1;" :: "r"(m), "r"(cnt) : "memory");
}
__device__ __forceinline__ void mbar_arrive(uint32_t m) {
    asm volatile("mbarrier.arrive.shared.b64 _, [%0];" :: "r"(m) : "memory");
}
__device__ __forceinline__ void mbar_wait(uint32_t m, uint32_t ph) {
    uint32_t done;
    asm volatile("{\n\t.reg .pred p;\n\t"
                 "mbarrier.try_wait.parity.acquire.cta.shared::cta.b64 p, [%1], %2;\n\t"
                 "selp.b32 %0, 1, 0, p;\n\t}"
                 : "=r"(done) : "r"(m), "r"(ph) : "memory");
    if (!done) {
        asm volatile("{\n\t.reg .pred P1;\n\t"
                     "WL_%=:\n\t"
                     "mbarrier.try_wait.parity.acquire.cta.shared::cta.b64 P1, [%0], %1, 0x989680;\n\t"
                     "@P1 bra.uni WD_%=;\n\t"
                     "bra.uni WL_%=;\n\t"
                     "WD_%=:\n\t}"
                     :: "r"(m), "r"(ph) : "memory");
    }
}
__device__ __forceinline__ float blkSum(float v, float* sbuf) {
    int lane = threadIdx.x & 31;
#pragma unroll
    for (int o = 16; o; o >>= 1) v += __shfl_xor_sync(0xffffffffu, v, o);
    __syncthreads();
    if (lane == 0) sbuf[threadIdx.x >> 5] = v;
    __syncthreads();
    int nw = blockDim.x >> 5;
    float r = (lane < nw) ? sbuf[lane] : 0.f;
#pragma unroll
    for (int o = 16; o; o >>= 1) r += __shfl_xor_sync(0xffffffffu, r, o);
    return r;
}

// ===================== warp-specialized fp16 GEMM (layer 0) =====================
// warps 0-7: consumers (64x32 warp tiles, LDSM + m16n8k16)
// warps 8-15: producers (LDG f32 -> silu/legendre/cvt -> STS fp16)
// MODE0: A' = silu(A), K = lda; producers also accumulate global min/max of raw A
//        into g_mm[0..1] (covers every element; 8x ntile redundancy is harmless).
// MODE1: A' = legendre(t(A)), K = 4*lda; t from g_mm[mmOff..mmOff+1].
template <int MODE>
__global__ void __launch_bounds__(NT_WS, 1) kal_gemm_ws(
    const float* __restrict__ A, int lda,
    const float* __restrict__ W, long ldw,
    float* __restrict__ Cp, int ldc, int ktiles, int mmOff)
{
    extern __shared__ char smem[];
    const uint32_t sb = smem_u32(smem);
    const int tid = threadIdx.x, lane = tid & 31, wid = tid >> 5;
    const int ntile = blockIdx.x, mtile = blockIdx.y, slab = blockIdx.z;
    const long kbase = (long)slab * ktiles * BK;

    if (tid == 0) {
#pragma unroll
        for (int s = 0; s < STAGES; s++) {
            mbar_init(sb + s * 16, 256);      // full: 256 producer threads
            mbar_init(sb + s * 16 + 8, 256);  // empty: 256 consumer threads
        }
    }
    __syncthreads();

    if (wid >= 8) {
        // ---- producer (256 threads) ----
        const int ptid = tid - 256;
        const int rowg = ptid >> 3, sub = ptid & 7;

        const float* asrc;
        float sA = 0.f, sBc = 0.f;
        if (MODE == 0) {
            asrc = A + (size_t)(mtile * BM + rowg) * lda + kbase + sub * 8;
        } else {
            asrc = A + (size_t)(mtile * BM + rowg) * lda + (kbase >> 2) + sub * 2;
            float xmin = decf(g_mm[mmOff]), xmax = decf(g_mm[mmOff + 1]);
            sA = 2.0f / (xmax - xmin);
            sBc = -sA * xmin - 1.0f;
        }
        const float* wsrc = W + (size_t)(ntile * BN + rowg) * ldw + kbase + sub * 8;

        uint32_t soff[4];
#pragma unroll
        for (int g = 0; g < 4; g++) {
            int r = rowg + g * 32;
            soff[g] = r * 128 + ((sub ^ (r & 7)) << 4);
        }

        float lo = FLT_MAX, hi = -FLT_MAX;   // MODE0 min/max of raw x

        int st = 0, ph = 1;
        for (int kt = 0; kt < ktiles; kt++) {
            mbar_wait(sb + st * 16 + 8, ph);
            char* ab = smem + SOFF_TILE + st * STAGE_BYTES;
            char* bb = ab + TILE_BYTES;
#pragma unroll
            for (int g = 0; g < 4; g++) {
                const float* p = wsrc + (size_t)g * 32 * ldw + (size_t)kt * BK;
                float4 w0 = *reinterpret_cast<const float4*>(p);
                float4 w1 = *reinterpret_cast<const float4*>(p + 4);
                *reinterpret_cast<uint4*>(bb + soff[g]) =
                    make_uint4(pack2(w0.x, w0.y), pack2(w0.z, w0.w),
                               pack2(w1.x, w1.y), pack2(w1.z, w1.w));
            }
            if (MODE == 0) {
#pragma unroll
                for (int g = 0; g < 4; g++) {
                    const float* p = asrc + (size_t)g * 32 * lda + (size_t)kt * BK;
                    float4 a0 = *reinterpret_cast<const float4*>(p);
                    float4 a1 = *reinterpret_cast<const float4*>(p + 4);
                    lo = fminf(lo, fminf(fminf(a0.x, a0.y), fminf(a0.z, a0.w)));
                    lo = fminf(lo, fminf(fminf(a1.x, a1.y), fminf(a1.z, a1.w)));
                    hi = fmaxf(hi, fmaxf(fmaxf(a0.x, a0.y), fmaxf(a0.z, a0.w)));
                    hi = fmaxf(hi, fmaxf(fmaxf(a1.x, a1.y), fmaxf(a1.z, a1.w)));
                    *reinterpret_cast<uint4*>(ab + soff[g]) =
                        make_uint4(pack2(silu(a0.x), silu(a0.y)),
                                   pack2(silu(a0.z), silu(a0.w)),
                                   pack2(silu(a1.x), silu(a1.y)),
                                   pack2(silu(a1.z), silu(a1.w)));
                }
            } else {
#pragma unroll
                for (int g = 0; g < 4; g++) {
                    float2 xv = *reinterpret_cast<const float2*>(
                        asrc + (size_t)g * 32 * lda + kt * 16);
                    float t0 = fmaf(xv.x, sA, sBc), t1 = fmaf(xv.y, sA, sBc);
                    float q0 = t0 * t0, q1 = t1 * t1;
                    *reinterpret_cast<uint4*>(ab + soff[g]) = make_uint4(
                        pack2(1.0f, t0),
                        pack2(fmaf(1.5f, q0, -0.5f), t0 * fmaf(2.5f, q0, -1.5f)),
                        pack2(1.0f, t1),
                        pack2(fmaf(1.5f, q1, -0.5f), t1 * fmaf(2.5f, q1, -1.5f)));
                }
            }
            mbar_arrive(sb + st * 16);
            if (++st == STAGES) { st = 0; ph ^= 1; }
        }

        if (MODE == 0) {
#pragma unroll
            for (int o = 16; o; o >>= 1) {
                lo = fminf(lo, __shfl_xor_sync(0xffffffffu, lo, o));
                hi = fmaxf(hi, __shfl_xor_sync(0xffffffffu, hi, o));
            }
            if (lane == 0) {
                atomicMin(&g_mm[0], encf(lo));
                atomicMax(&g_mm[1], encf(hi));
            }
        }
    } else {
        // ---- consumer (8 warps, 64x32 tiles) ----
        const int wm0 = (wid & 1) * 64, wn0 = (wid >> 1) * 32;
        const int rr = lane >> 2, cc = lane & 3;
        const int h7 = lane & 7;
        const int a_row = (lane & 15);
        const int a_hi = lane >> 4;
        const int b_rowoff = ((lane >> 4) << 3) + h7;
        const int b_hi = (lane >> 3) & 1;

        float acc[4][4][4] = {};

        int st = 0, ph = 0;
        for (int kt = 0; kt < ktiles; kt++) {
            mbar_wait(sb + st * 16, ph);
            const uint32_t abase = sb + SOFF_TILE + st * STAGE_BYTES;
            const uint32_t bbase = abase + TILE_BYTES;
#pragma unroll
            for (int kc = 0; kc < 4; kc++) {
                unsigned af[4][4];
#pragma unroll
                for (int i = 0; i < 4; i++) {
                    uint32_t addr = abase + (wm0 + i * 16 + a_row) * 128 +
                                    (((2 * kc + a_hi) ^ h7) << 4);
                    asm volatile(
                        "ldmatrix.sync.aligned.m8n8.x4.shared.b16 {%0,%1,%2,%3}, [%4];"
                        : "=r"(af[i][0]), "=r"(af[i][1]), "=r"(af[i][2]), "=r"(af[i][3])
                        : "r"(addr));
                }
                unsigned bfr[8];
#pragma unroll
                for (int jj = 0; jj < 2; jj++) {
                    uint32_t addr = bbase + (wn0 + jj * 16 + b_rowoff) * 128 +
                                    (((2 * kc + b_hi) ^ h7) << 4);
                    asm volatile(
                        "ldmatrix.sync.aligned.m8n8.x4.shared.b16 {%0,%1,%2,%3}, [%4];"
                        : "=r"(bfr[jj * 4]), "=r"(bfr[jj * 4 + 1]),
                          "=r"(bfr[jj * 4 + 2]), "=r"(bfr[jj * 4 + 3])
                        : "r"(addr));
                }
#pragma unroll
                for (int j = 0; j < 4; j++) {
                    unsigned b0 = bfr[(j >> 1) * 4 + (j & 1) * 2];
                    unsigned b1 = bfr[(j >> 1) * 4 + (j & 1) * 2 + 1];
#pragma unroll
                    for (int i = 0; i < 4; i++) {
                        asm volatile(
                            "mma.sync.aligned.m16n8k16.row.col.f32.f16.f16.f32 "
                            "{%0,%1,%2,%3}, {%4,%5,%6,%7}, {%8,%9}, {%0,%1,%2,%3};"
                            : "+f"(acc[i][j][0]), "+f"(acc[i][j][1]),
                              "+f"(acc[i][j][2]), "+f"(acc[i][j][3])
                            : "r"(af[i][0]), "r"(af[i][1]), "r"(af[i][2]), "r"(af[i][3]),
                              "r"(b0), "r"(b1));
                    }
                }
            }
            mbar_arrive(sb + st * 16 + 8);
            if (++st == STAGES) { st = 0; ph ^= 1; }
        }

        const int c2 = cc * 2;
#pragma unroll
        for (int i = 0; i < 4; i++) {
            int row = mtile * BM + wm0 + i * 16 + rr;
#pragma unroll
            for (int j = 0; j < 4; j++) {
                int col = ntile * BN + wn0 + j * 8 + c2;
                size_t o = ((size_t)slab * B_SZ + row) * (size_t)ldc + col;
                *reinterpret_cast<float2*>(&Cp[o]) = make_float2(acc[i][j][0], acc[i][j][1]);
                *reinterpret_cast<float2*>(&Cp[o + 8 * (size_t)ldc]) =
                    make_float2(acc[i][j][2], acc[i][j][3]);
            }
        }
    }
}

// ===================== bulk-sync fp16 GEMM (layer-1, small) =====================
template <int MODE>
__global__ void __launch_bounds__(NT_BS, 2) kal_gemm_bs(
    const float* __restrict__ A, int lda,
    const float* __restrict__ W, long ldw,
    float* __restrict__ Cp, int ldc, int ktiles, int mmOff)
{
    extern __shared__ char smem[];
    const int tid = threadIdx.x, lane = tid & 31, wid = tid >> 5;
    const int wm0 = (wid & 1) * 64, wn0 = (wid >> 1) * 32;
    const int rr = lane >> 2, cc = lane & 3;
    const int ntile = blockIdx.x, mtile = blockIdx.y, slab = blockIdx.z;
    const long kbase = (long)slab * ktiles * BK;

    const int rowg = tid >> 3, sub = tid & 7;
    const int h7 = lane & 7;
    const int a_row = (lane & 15);
    const int a_hi = lane >> 4;
    const int b_rowoff = ((lane >> 4) << 3) + h7;
    const int b_hi = (lane >> 3) & 1;

    const float* asrc;
    float sA = 0.f, sBc = 0.f;
    if (MODE == 0) {
        asrc = A + (size_t)(mtile * BM + rowg) * lda + kbase + sub * 8;
    } else {
        asrc = A + (size_t)(mtile * BM + rowg) * lda + (kbase >> 2) + sub * 2;
        float xmin = decf(g_mm[mmOff]), xmax = decf(g_mm[mmOff + 1]);
        sA = 2.0f / (xmax - xmin);
        sBc = -sA * xmin - 1.0f;
    }
    const float* wsrc = W + (size_t)(ntile * BN + rowg) * ldw + kbase + sub * 8;

    uint32_t soff[4];
#pragma unroll
    for (int g = 0; g < 4; g++) {
        int r = rowg + g * 32;
        soff[g] = r * 128 + ((sub ^ (r & 7)) << 4);
    }

    uint4 aS[4], bS[4];

    auto ldcvtB = [&](int kt) {
#pragma unroll
        for (int g = 0; g < 4; g++) {
            const float* p = wsrc + (size_t)g * 32 * ldw + (size_t)kt * BK;
            float4 w0 = *reinterpret_cast<const float4*>(p);
            float4 w1 = *reinterpret_cast<const float4*>(p + 4);
            bS[g] = make_uint4(pack2(w0.x, w0.y), pack2(w0.z, w0.w),
                               pack2(w1.x, w1.y), pack2(w1.z, w1.w));
        }
    };
    auto ldcvtA = [&](int kt) {
        if (MODE == 0) {
#pragma unroll
            for (int g = 0; g < 4; g++) {
                const float* p = asrc + (size_t)g * 32 * lda + (size_t)kt * BK;
                float4 a0 = *reinterpret_cast<const float4*>(p);
                float4 a1 = *reinterpret_cast<const float4*>(p + 4);
                aS[g] = make_uint4(pack2(silu(a0.x), silu(a0.y)),
                                   pack2(silu(a0.z), silu(a0.w)),
                                   pack2(silu(a1.x), silu(a1.y)),
                                   pack2(silu(a1.z), silu(a1.w)));
            }
        } else {
#pragma unroll
            for (int g = 0; g < 4; g++) {
                float2 xv = *reinterpret_cast<const float2*>(
                    asrc + (size_t)g * 32 * lda + kt * 16);
                float t0 = fmaf(xv.x, sA, sBc), t1 = fmaf(xv.y, sA, sBc);
                float q0 = t0 * t0, q1 = t1 * t1;
                aS[g] = make_uint4(
                    pack2(1.0f, t0),
                    pack2(fmaf(1.5f, q0, -0.5f), t0 * fmaf(2.5f, q0, -1.5f)),
                    pack2(1.0f, t1),
                    pack2(fmaf(1.5f, q1, -0.5f), t1 * fmaf(2.5f, q1, -1.5f)));
            }
        }
    };
    auto stA = [&](char* ast) {
#pragma unroll
        for (int g = 0; g < 4; g++) *reinterpret_cast<uint4*>(ast + soff[g]) = aS[g];
    };
    auto stB = [&](char* bst) {
#pragma unroll
        for (int g = 0; g < 4; g++) *reinterpret_cast<uint4*>(bst + soff[g]) = bS[g];
    };

    float acc[4][4][4] = {};

    auto compute = [&](const char* Ast, const char* Bst) {
        const uint32_t abase = (uint32_t)__cvta_generic_to_shared(Ast);
        const uint32_t bbase = (uint32_t)__cvta_generic_to_shared(Bst);
#pragma unroll
        for (int kc = 0; kc < 4; kc++) {
            unsigned af[4][4];
#pragma unroll
            for (int i = 0; i < 4; i++) {
                uint32_t addr = abase + (wm0 + i * 16 + a_row) * 128 +
                                (((2 * kc + a_hi) ^ h7) << 4);
                asm volatile(
                    "ldmatrix.sync.aligned.m8n8.x4.shared.b16 {%0,%1,%2,%3}, [%4];"
                    : "=r"(af[i][0]), "=r"(af[i][1]), "=r"(af[i][2]), "=r"(af[i][3])
                    : "r"(addr));
            }
            unsigned bfr[8];
#pragma unroll
            for (int jj = 0; jj < 2; jj++) {
                uint32_t addr = bbase + (wn0 + jj * 16 + b_rowoff) * 128 +
                                (((2 * kc + b_hi) ^ h7) << 4);
                asm volatile(
                    "ldmatrix.sync.aligned.m8n8.x4.shared.b16 {%0,%1,%2,%3}, [%4];"
                    : "=r"(bfr[jj * 4]), "=r"(bfr[jj * 4 + 1]),
                      "=r"(bfr[jj * 4 + 2]), "=r"(bfr[jj * 4 + 3])
                    : "r"(addr));
            }
#pragma unroll
            for (int j = 0; j < 4; j++) {
                unsigned b0 = bfr[(j >> 1) * 4 + (j & 1) * 2];
                unsigned b1 = bfr[(j >> 1) * 4 + (j & 1) * 2 + 1];
#pragma unroll
                for (int i = 0; i < 4; i++) {
                    asm volatile(
                        "mma.sync.aligned.m16n8k16.row.col.f32.f16.f16.f32 "
                        "{%0,%1,%2,%3}, {%4,%5,%6,%7}, {%8,%9}, {%0,%1,%2,%3};"
                        : "+f"(acc[i][j][0]), "+f"(acc[i][j][1]),
                          "+f"(acc[i][j][2]), "+f"(acc[i][j][3])
                        : "r"(af[i][0]), "r"(af[i][1]), "r"(af[i][2]), "r"(af[i][3]),
                          "r"(b0), "r"(b1));
                }
            }
        }
    };

    char* Abuf[2] = { smem, smem + TILE_BYTES };
    char* Bbuf[2] = { smem + 2 * TILE_BYTES, smem + 3 * TILE_BYTES };

    ldcvtA(0); ldcvtB(0);
    stA(Abuf[0]); stB(Bbuf[0]);
    __syncthreads();

    for (int kt = 0; kt < ktiles; kt++) {
        const int cur = kt & 1;
        const bool more = (kt + 1) < ktiles;
        compute(Abuf[cur], Bbuf[cur]);
        if (more) {
            ldcvtA(kt + 1); ldcvtB(kt + 1);
            stA(Abuf[cur ^ 1]); stB(Bbuf[cur ^ 1]);
        }
        __syncthreads();
    }

    const int c2 = cc * 2;
#pragma unroll
    for (int i = 0; i < 4; i++) {
        int row = mtile * BM + wm0 + i * 16 + rr;
#pragma unroll
        for (int j = 0; j < 4; j++) {
            int col = ntile * BN + wn0 + j * 8 + c2;
            size_t o = ((size_t)slab * B_SZ + row) * (size_t)ldc + col;
            *reinterpret_cast<float2*>(&Cp[o]) = make_float2(acc[i][j][0], acc[i][j][1]);
            *reinterpret_cast<float2*>(&Cp[o + 8 * (size_t)ldc]) =
                make_float2(acc[i][j][2], acc[i][j][3]);
        }
    }
}

// ===================== small kernels =====================
__global__ void k_init() {
    g_mm[0] = encf(FLT_MAX); g_mm[1] = encf(-FLT_MAX);
    g_mm[2] = encf(FLT_MAX); g_mm[3] = encf(-FLT_MAX);
}

// 512 threads, float2 per thread (2 contiguous columns)
__global__ void k_reduce_ln0(const float* __restrict__ part,
                             const float* __restrict__ gamma,
                             const float* __restrict__ beta) {
    const int b = blockIdx.x, tid = threadIdx.x;
    float2 hv = make_float2(0.f, 0.f);
    for (int s = 0; s < S0_TOT; s++) {
        float2 v = *reinterpret_cast<const float2*>(
            &part[((size_t)s * B_SZ + b) * D1 + tid * 2]);
        hv.x += v.x; hv.y += v.y;
    }
    __shared__ float sbuf[32];
    float mean = blkSum(hv.x + hv.y, sbuf) * (1.0f / D1);
    float dx = hv.x - mean, dy = hv.y - mean;
    float inv = rsqrtf(blkSum(dx * dx + dy * dy, sbuf) * (1.0f / D1) + 1e-5f);
    float2 gv = *reinterpret_cast<const float2*>(&gamma[tid * 2]);
    float2 bv = *reinterpret_cast<const float2*>(&beta[tid * 2]);
    float a0 = silu(dx * inv * gv.x + bv.x);
    float a1 = silu(dy * inv * gv.y + bv.y);
    *reinterpret_cast<float2*>(&g_h0[b * D1 + tid * 2]) = make_float2(a0, a1);
    float lo = fminf(a0, a1), hi = fmaxf(a0, a1);
#pragma unroll
    for (int o = 16; o; o >>= 1) {
        lo = fminf(lo, __shfl_xor_sync(0xffffffffu, lo, o));
        hi = fmaxf(hi, __shfl_xor_sync(0xffffffffu, hi, o));
    }
    __shared__ float slo[16], shi[16];
    if ((tid & 31) == 0) { slo[tid >> 5] = lo; shi[tid >> 5] = hi; }
    __syncthreads();
    if (tid == 0) {
#pragma unroll
        for (int w = 1; w < 16; w++) { lo = fminf(lo, slo[w]); hi = fmaxf(hi, shi[w]); }
        atomicMin(&g_mm[2], encf(lo));
        atomicMax(&g_mm[3], encf(hi));
    }
}

__global__ void k_reduce_ln1(const float* __restrict__ part,
                             const float* __restrict__ gamma,
                             const float* __restrict__ beta,
                             const float* __restrict__ ow,
                             const float* __restrict__ ob,
                             float* __restrict__ out) {
    const int b = blockIdx.x, tid = threadIdx.x;  // 128 threads
    float acc = 0.f;
    for (int s = 0; s < SL1_TOT; s++) acc += part[((size_t)s * B_SZ + b) * D2 + tid];
    __shared__ float sbuf[32];
    float mean = blkSum(acc, sbuf) * (1.0f / D2);
    float d = acc - mean;
    float var = blkSum(d * d, sbuf) * (1.0f / D2);
    float y = d * rsqrtf(var + 1e-5f) * gamma[tid] + beta[tid];
    float a = silu(y);
    float l0 = blkSum(a * ow[tid], sbuf);
    float l1 = blkSum(a * ow[128 + tid], sbuf);
    if (tid == 0) {
        l0 += ob[0]; l1 += ob[1];
        float m = fmaxf(l0, l1);
        float e0 = expf(l0 - m), e1 = expf(l1 - m);
        float inv = 1.f / (e0 + e1);
        out[b * 2 + 0] = e0 * inv;
        out[b * 2 + 1] = e1 * inv;
    }
}

extern "C" void kernel_launch(void* const* d_in, const int* in_sizes, int n_in,
                              void* d_out, int out_size) {
    (void)in_sizes; (void)n_in; (void)out_size;
    const float* x       = (const float*)d_in[0];
    const float* base_w0 = (const float*)d_in[1];
    const float* poly_w0 = (const float*)d_in[2];
    const float* ln_g0   = (const float*)d_in[3];
    const float* ln_b0   = (const float*)d_in[4];
    const float* base_w1 = (const float*)d_in[5];
    const float* poly_w1 = (const float*)d_in[6];
    const float* ln_g1   = (const float*)d_in[7];
    const float* ln_b1   = (const float*)d_in[8];
    const float* out_w   = (const float*)d_in[9];
    const float* out_b   = (const float*)d_in[10];
    float* out = (float*)d_out;

    float *part0, *part1, *h0;
    cudaGetSymbolAddress((void**)&part0, g_part0);
    cudaGetSymbolAddress((void**)&part1, g_part1);
    cudaGetSymbolAddress((void**)&h0, g_h0);

    cudaFuncSetAttribute(kal_gemm_ws<0>, cudaFuncAttributeMaxDynamicSharedMemorySize, SMEM_WS);
    cudaFuncSetAttribute(kal_gemm_ws<1>, cudaFuncAttributeMaxDynamicSharedMemorySize, SMEM_WS);
    cudaFuncSetAttribute(kal_gemm_bs<0>, cudaFuncAttributeMaxDynamicSharedMemorySize, SMEM_BS);
    cudaFuncSetAttribute(kal_gemm_bs<1>, cudaFuncAttributeMaxDynamicSharedMemorySize, SMEM_BS);

    k_init<<<1, 1>>>();

    // layer 0: ws<0> first (also computes global min/max of x into g_mm[0..1]),
    // then ws<1> consumes g_mm.
    kal_gemm_ws<0><<<dim3(8, 2, S1), NT_WS, SMEM_WS>>>(x, D0, base_w0, D0,
                                                       part0, D1, KT1, 0);
    kal_gemm_ws<1><<<dim3(8, 2, S2), NT_WS, SMEM_WS>>>(x, D0, poly_w0, (long)D0 * 4,
                                                       part0 + (size_t)S1 * B_SZ * D1,
                                                       D1, KT2, 0);
    k_reduce_ln0<<<B_SZ, 512>>>(part0, ln_g0, ln_b0);

    // layer 1 (small): bulk-sync
    kal_gemm_bs<0><<<dim3(1, 2, S3), NT_BS, SMEM_BS>>>(h0, D1, base_w1, D1,
                                                       part1, D2, KT3, 2);
    kal_gemm_bs<1><<<dim3(1, 2, S4), NT_BS, SMEM_BS>>>(h0, D1, poly_w1, (long)D1 * 4,
                                                       part1 + (size_t)S3 * B_SZ * D2,
                                                       D2, KT4, 2);
    k_reduce_ln1<<<B_SZ, 128>>>(part1, ln_g1, ln_b1, out_w, out_b, out);
}

// round 15
// speedup vs baseline: 1.0496x; 1.0496x over previous
#include <cuda_runtime.h>
#include <cuda_fp16.h>
#include <math.h>
#include <float.h>
#include <stdint.h>

#define B_SZ 256
#define D0 50176
#define D1 1024
#define D2 128
#define BM 128
#define BN 128
#define BK 64               // K fp16 elements per tile (128B rows)

#define NT_BS 256
#define NT_WS 512           // 8 consumer warps + 8 producer warps
#define STAGES 4

// layer0 merged grid: poly 64 slabs x 49 kt [z 0..63]; base 28 slabs x 28 kt [z 64..91]
#define S2 64
#define KT2 49
#define S1 28
#define KT1 28
#define S0_TOT (S2 + S1)    // 92
// layer1 (bulk-sync)
#define S3 8
#define KT3 2
#define S4 16
#define KT4 4
#define SL1_TOT (S3 + S4)

#define TILE_BYTES 16384
#define SMEM_BS (4 * TILE_BYTES)
#define STAGE_BYTES (2 * TILE_BYTES)
#define SOFF_TILE 1024
#define SMEM_WS (SOFF_TILE + STAGES * STAGE_BYTES)  // 132096

__device__ float    g_part0[(size_t)S0_TOT * B_SZ * D1];
__device__ float    g_part1[(size_t)SL1_TOT * B_SZ * D2];
__device__ float    g_h0[B_SZ * D1];
__device__ unsigned g_mm[4];

__device__ __forceinline__ unsigned encf(float f) {
    unsigned u = __float_as_uint(f);
    return (u & 0x80000000u) ? ~u : (u | 0x80000000u);
}
__device__ __forceinline__ float decf(unsigned u) {
    u = (u & 0x80000000u) ? (u & 0x7FFFFFFFu) : ~u;
    return __uint_as_float(u);
}
__device__ __forceinline__ uint32_t pack2(float a, float b) {
    __half2 h = __floats2half2_rn(a, b);
    return *reinterpret_cast<uint32_t*>(&h);
}
__device__ __forceinline__ float silu(float a) {
    return __fdividef(a, 1.0f + __expf(-a));
}
__device__ __forceinline__ uint32_t smem_u32(const void* p) {
    uint32_t a;
    asm("{ .reg .u64 t; cvta.to.shared.u64 t, %1; cvt.u32.u64 %0, t; }" : "=r"(a) : "l"(p));
    return a;
}
__device__ __forceinline__ void mbar_init(uint32_t m, uint32_t cnt) {
    asm volatile("mbarrier.init.shared.b64 [%0], %1;" :: "r"(m), "r"(cnt) : "memory");
}
__device__ __forceinline__ void mbar_arrive(uint32_t m) {
    asm volatile("mbarrier.arrive.shared.b64 _, [%0];" :: "r"(m) : "memory");
}
__device__ __forceinline__ void mbar_wait(uint32_t m, uint32_t ph) {
    uint32_t done;
    asm volatile("{\n\t.reg .pred p;\n\t"
                 "mbarrier.try_wait.parity.acquire.cta.shared::cta.b64 p, [%1], %2;\n\t"
                 "selp.b32 %0, 1, 0, p;\n\t}"
                 : "=r"(done) : "r"(m), "r"(ph) : "memory");
    if (!done) {
        asm volatile("{\n\t.reg .pred P1;\n\t"
                     "WL_%=:\n\t"
                     "mbarrier.try_wait.parity.acquire.cta.shared::cta.b64 P1, [%0], %1, 0x989680;\n\t"
                     "@P1 bra.uni WD_%=;\n\t"
                     "bra.uni WL_%=;\n\t"
                     "WD_%=:\n\t}"
                     :: "r"(m), "r"(ph) : "memory");
    }
}
__device__ __forceinline__ float blkSum(float v, float* sbuf) {
    int lane = threadIdx.x & 31;
#pragma unroll
    for (int o = 16; o; o >>= 1) v += __shfl_xor_sync(0xffffffffu, v, o);
    __syncthreads();
    if (lane == 0) sbuf[threadIdx.x >> 5] = v;
    __syncthreads();
    int nw = blockDim.x >> 5;
    float r = (lane < nw) ? sbuf[lane] : 0.f;
#pragma unroll
    for (int o = 16; o; o >>= 1) r += __shfl_xor_sync(0xffffffffu, r, o);
    return r;
}

// ---- producer fill loop, fully specialized per MODE (compile-time strides) ----
template <int MODE>
__device__ __forceinline__ void l0_produce(
    const float* __restrict__ A, const float* __restrict__ W,
    char* smem, uint32_t sb, int ntile, int mtile, long kbase, int ktiles, int ptid)
{
    const int rowg = ptid >> 3, sub = ptid & 7;
    constexpr long LDW = MODE ? (long)D0 * 4 : (long)D0;

    const float* asrc;
    float sA = 0.f, sBc = 0.f;
    if (MODE == 0) {
        asrc = A + (size_t)(mtile * BM + rowg) * D0 + kbase + sub * 8;
    } else {
        asrc = A + (size_t)(mtile * BM + rowg) * D0 + (kbase >> 2) + sub * 2;
        float xmin = decf(g_mm[0]), xmax = decf(g_mm[1]);
        sA = 2.0f / (xmax - xmin);
        sBc = -sA * xmin - 1.0f;
    }
    const float* wsrc = W + (size_t)(ntile * BN + rowg) * LDW + kbase + sub * 8;

    uint32_t soff[4];
#pragma unroll
    for (int g = 0; g < 4; g++) {
        int r = rowg + g * 32;
        soff[g] = r * 128 + ((sub ^ (r & 7)) << 4);
    }

    int st = 0, ph = 1;
    for (int kt = 0; kt < ktiles; kt++) {
        mbar_wait(sb + st * 16 + 8, ph);
        char* ab = smem + SOFF_TILE + st * STAGE_BYTES;
        char* bb = ab + TILE_BYTES;
#pragma unroll
        for (int g = 0; g < 4; g++) {
            const float* p = wsrc + (size_t)g * 32 * LDW + (size_t)kt * BK;
            float4 w0 = *reinterpret_cast<const float4*>(p);
            float4 w1 = *reinterpret_cast<const float4*>(p + 4);
            *reinterpret_cast<uint4*>(bb + soff[g]) =
                make_uint4(pack2(w0.x, w0.y), pack2(w0.z, w0.w),
                           pack2(w1.x, w1.y), pack2(w1.z, w1.w));
        }
        if (MODE == 0) {
#pragma unroll
            for (int g = 0; g < 4; g++) {
                const float* p = asrc + (size_t)g * 32 * D0 + (size_t)kt * BK;
                float4 a0 = *reinterpret_cast<const float4*>(p);
                float4 a1 = *reinterpret_cast<const float4*>(p + 4);
                *reinterpret_cast<uint4*>(ab + soff[g]) =
                    make_uint4(pack2(silu(a0.x), silu(a0.y)),
                               pack2(silu(a0.z), silu(a0.w)),
                               pack2(silu(a1.x), silu(a1.y)),
                               pack2(silu(a1.z), silu(a1.w)));
            }
        } else {
#pragma unroll
            for (int g = 0; g < 4; g++) {
                float2 xv = *reinterpret_cast<const float2*>(
                    asrc + (size_t)g * 32 * D0 + kt * 16);
                float t0 = fmaf(xv.x, sA, sBc), t1 = fmaf(xv.y, sA, sBc);
                float q0 = t0 * t0, q1 = t1 * t1;
                *reinterpret_cast<uint4*>(ab + soff[g]) = make_uint4(
                    pack2(1.0f, t0),
                    pack2(fmaf(1.5f, q0, -0.5f), t0 * fmaf(2.5f, q0, -1.5f)),
                    pack2(1.0f, t1),
                    pack2(fmaf(1.5f, q1, -0.5f), t1 * fmaf(2.5f, q1, -1.5f)));
            }
        }
        mbar_arrive(sb + st * 16);
        if (++st == STAGES) { st = 0; ph ^= 1; }
    }
}

// ===================== merged layer-0 warp-specialized GEMM =====================
// z < S2: poly slab z (49 kt); z >= S2: base slab z-S2 (28 kt).
// warps 0-7 consumers (MODE-independent), warps 8-15 producers (templated dispatch).
__global__ void __launch_bounds__(NT_WS, 1) kal_l0(
    const float* __restrict__ A,
    const float* __restrict__ BW, const float* __restrict__ PW,
    float* __restrict__ Cp)
{
    extern __shared__ char smem[];
    const uint32_t sb = smem_u32(smem);
    const int tid = threadIdx.x, lane = tid & 31, wid = tid >> 5;
    const int ntile = blockIdx.x, mtile = blockIdx.y, z = blockIdx.z;
    const int mode1 = (z < S2);
    const int ktiles = mode1 ? KT2 : KT1;

    if (tid == 0) {
#pragma unroll
        for (int s = 0; s < STAGES; s++) {
            mbar_init(sb + s * 16, 256);      // full
            mbar_init(sb + s * 16 + 8, 256);  // empty
        }
    }
    __syncthreads();

    if (wid >= 8) {
        if (mode1)
            l0_produce<1>(A, PW, smem, sb, ntile, mtile, (long)z * KT2 * BK, KT2, tid - 256);
        else
            l0_produce<0>(A, BW, smem, sb, ntile, mtile, (long)(z - S2) * KT1 * BK, KT1, tid - 256);
    } else {
        // ---- consumer (8 warps, 64x32 tiles), MODE-independent ----
        const int wm0 = (wid & 1) * 64, wn0 = (wid >> 1) * 32;
        const int rr = lane >> 2, cc = lane & 3;
        const int h7 = lane & 7;
        const int a_row = (lane & 15);
        const int a_hi = lane >> 4;
        const int b_rowoff = ((lane >> 4) << 3) + h7;
        const int b_hi = (lane >> 3) & 1;

        float acc[4][4][4] = {};

        int st = 0, ph = 0;
        for (int kt = 0; kt < ktiles; kt++) {
            mbar_wait(sb + st * 16, ph);
            const uint32_t abase = sb + SOFF_TILE + st * STAGE_BYTES;
            const uint32_t bbase = abase + TILE_BYTES;
#pragma unroll
            for (int kc = 0; kc < 4; kc++) {
                unsigned af[4][4];
#pragma unroll
                for (int i = 0; i < 4; i++) {
                    uint32_t addr = abase + (wm0 + i * 16 + a_row) * 128 +
                                    (((2 * kc + a_hi) ^ h7) << 4);
                    asm volatile(
                        "ldmatrix.sync.aligned.m8n8.x4.shared.b16 {%0,%1,%2,%3}, [%4];"
                        : "=r"(af[i][0]), "=r"(af[i][1]), "=r"(af[i][2]), "=r"(af[i][3])
                        : "r"(addr));
                }
                unsigned bfr[8];
#pragma unroll
                for (int jj = 0; jj < 2; jj++) {
                    uint32_t addr = bbase + (wn0 + jj * 16 + b_rowoff) * 128 +
                                    (((2 * kc + b_hi) ^ h7) << 4);
                    asm volatile(
                        "ldmatrix.sync.aligned.m8n8.x4.shared.b16 {%0,%1,%2,%3}, [%4];"
                        : "=r"(bfr[jj * 4]), "=r"(bfr[jj * 4 + 1]),
                          "=r"(bfr[jj * 4 + 2]), "=r"(bfr[jj * 4 + 3])
                        : "r"(addr));
                }
#pragma unroll
                for (int j = 0; j < 4; j++) {
                    unsigned b0 = bfr[(j >> 1) * 4 + (j & 1) * 2];
                    unsigned b1 = bfr[(j >> 1) * 4 + (j & 1) * 2 + 1];
#pragma unroll
                    for (int i = 0; i < 4; i++) {
                        asm volatile(
                            "mma.sync.aligned.m16n8k16.row.col.f32.f16.f16.f32 "
                            "{%0,%1,%2,%3}, {%4,%5,%6,%7}, {%8,%9}, {%0,%1,%2,%3};"
                            : "+f"(acc[i][j][0]), "+f"(acc[i][j][1]),
                              "+f"(acc[i][j][2]), "+f"(acc[i][j][3])
                            : "r"(af[i][0]), "r"(af[i][1]), "r"(af[i][2]), "r"(af[i][3]),
                              "r"(b0), "r"(b1));
                    }
                }
            }
            mbar_arrive(sb + st * 16 + 8);
            if (++st == STAGES) { st = 0; ph ^= 1; }
        }

        const int c2 = cc * 2;
#pragma unroll
        for (int i = 0; i < 4; i++) {
            int row = mtile * BM + wm0 + i * 16 + rr;
#pragma unroll
            for (int j = 0; j < 4; j++) {
                int col = ntile * BN + wn0 + j * 8 + c2;
                size_t o = ((size_t)z * B_SZ + row) * (size_t)D1 + col;
                *reinterpret_cast<float2*>(&Cp[o]) = make_float2(acc[i][j][0], acc[i][j][1]);
                *reinterpret_cast<float2*>(&Cp[o + 8 * (size_t)D1]) =
                    make_float2(acc[i][j][2], acc[i][j][3]);
            }
        }
    }
}

// ===================== bulk-sync fp16 GEMM (layer-1, small) =====================
template <int MODE>
__global__ void __launch_bounds__(NT_BS, 2) kal_gemm_bs(
    const float* __restrict__ A, int lda,
    const float* __restrict__ W, long ldw,
    float* __restrict__ Cp, int ldc, int ktiles, int mmOff)
{
    extern __shared__ char smem[];
    const int tid = threadIdx.x, lane = tid & 31, wid = tid >> 5;
    const int wm0 = (wid & 1) * 64, wn0 = (wid >> 1) * 32;
    const int rr = lane >> 2, cc = lane & 3;
    const int ntile = blockIdx.x, mtile = blockIdx.y, slab = blockIdx.z;
    const long kbase = (long)slab * ktiles * BK;

    const int rowg = tid >> 3, sub = tid & 7;
    const int h7 = lane & 7;
    const int a_row = (lane & 15);
    const int a_hi = lane >> 4;
    const int b_rowoff = ((lane >> 4) << 3) + h7;
    const int b_hi = (lane >> 3) & 1;

    const float* asrc;
    float sA = 0.f, sBc = 0.f;
    if (MODE == 0) {
        asrc = A + (size_t)(mtile * BM + rowg) * lda + kbase + sub * 8;
    } else {
        asrc = A + (size_t)(mtile * BM + rowg) * lda + (kbase >> 2) + sub * 2;
        float xmin = decf(g_mm[mmOff]), xmax = decf(g_mm[mmOff + 1]);
        sA = 2.0f / (xmax - xmin);
        sBc = -sA * xmin - 1.0f;
    }
    const float* wsrc = W + (size_t)(ntile * BN + rowg) * ldw + kbase + sub * 8;

    uint32_t soff[4];
#pragma unroll
    for (int g = 0; g < 4; g++) {
        int r = rowg + g * 32;
        soff[g] = r * 128 + ((sub ^ (r & 7)) << 4);
    }

    uint4 aS[4], bS[4];

    auto ldcvtB = [&](int kt) {
#pragma unroll
        for (int g = 0; g < 4; g++) {
            const float* p = wsrc + (size_t)g * 32 * ldw + (size_t)kt * BK;
            float4 w0 = *reinterpret_cast<const float4*>(p);
            float4 w1 = *reinterpret_cast<const float4*>(p + 4);
            bS[g] = make_uint4(pack2(w0.x, w0.y), pack2(w0.z, w0.w),
                               pack2(w1.x, w1.y), pack2(w1.z, w1.w));
        }
    };
    auto ldcvtA = [&](int kt) {
        if (MODE == 0) {
#pragma unroll
            for (int g = 0; g < 4; g++) {
                const float* p = asrc + (size_t)g * 32 * lda + (size_t)kt * BK;
                float4 a0 = *reinterpret_cast<const float4*>(p);
                float4 a1 = *reinterpret_cast<const float4*>(p + 4);
                aS[g] = make_uint4(pack2(silu(a0.x), silu(a0.y)),
                                   pack2(silu(a0.z), silu(a0.w)),
                                   pack2(silu(a1.x), silu(a1.y)),
                                   pack2(silu(a1.z), silu(a1.w)));
            }
        } else {
#pragma unroll
            for (int g = 0; g < 4; g++) {
                float2 xv = *reinterpret_cast<const float2*>(
                    asrc + (size_t)g * 32 * lda + kt * 16);
                float t0 = fmaf(xv.x, sA, sBc), t1 = fmaf(xv.y, sA, sBc);
                float q0 = t0 * t0, q1 = t1 * t1;
                aS[g] = make_uint4(
                    pack2(1.0f, t0),
                    pack2(fmaf(1.5f, q0, -0.5f), t0 * fmaf(2.5f, q0, -1.5f)),
                    pack2(1.0f, t1),
                    pack2(fmaf(1.5f, q1, -0.5f), t1 * fmaf(2.5f, q1, -1.5f)));
            }
        }
    };
    auto stA = [&](char* ast) {
#pragma unroll
        for (int g = 0; g < 4; g++) *reinterpret_cast<uint4*>(ast + soff[g]) = aS[g];
    };
    auto stB = [&](char* bst) {
#pragma unroll
        for (int g = 0; g < 4; g++) *reinterpret_cast<uint4*>(bst + soff[g]) = bS[g];
    };

    float acc[4][4][4] = {};

    auto compute = [&](const char* Ast, const char* Bst) {
        const uint32_t abase = (uint32_t)__cvta_generic_to_shared(Ast);
        const uint32_t bbase = (uint32_t)__cvta_generic_to_shared(Bst);
#pragma unroll
        for (int kc = 0; kc < 4; kc++) {
            unsigned af[4][4];
#pragma unroll
            for (int i = 0; i < 4; i++) {
                uint32_t addr = abase + (wm0 + i * 16 + a_row) * 128 +
                                (((2 * kc + a_hi) ^ h7) << 4);
                asm volatile(
                    "ldmatrix.sync.aligned.m8n8.x4.shared.b16 {%0,%1,%2,%3}, [%4];"
                    : "=r"(af[i][0]), "=r"(af[i][1]), "=r"(af[i][2]), "=r"(af[i][3])
                    : "r"(addr));
            }
            unsigned bfr[8];
#pragma unroll
            for (int jj = 0; jj < 2; jj++) {
                uint32_t addr = bbase + (wn0 + jj * 16 + b_rowoff) * 128 +
                                (((2 * kc + b_hi) ^ h7) << 4);
                asm volatile(
                    "ldmatrix.sync.aligned.m8n8.x4.shared.b16 {%0,%1,%2,%3}, [%4];"
                    : "=r"(bfr[jj * 4]), "=r"(bfr[jj * 4 + 1]),
                      "=r"(bfr[jj * 4 + 2]), "=r"(bfr[jj * 4 + 3])
                    : "r"(addr));
            }
#pragma unroll
            for (int j = 0; j < 4; j++) {
                unsigned b0 = bfr[(j >> 1) * 4 + (j & 1) * 2];
                unsigned b1 = bfr[(j >> 1) * 4 + (j & 1) * 2 + 1];
#pragma unroll
                for (int i = 0; i < 4; i++) {
                    asm volatile(
                        "mma.sync.aligned.m16n8k16.row.col.f32.f16.f16.f32 "
                        "{%0,%1,%2,%3}, {%4,%5,%6,%7}, {%8,%9}, {%0,%1,%2,%3};"
                        : "+f"(acc[i][j][0]), "+f"(acc[i][j][1]),
                          "+f"(acc[i][j][2]), "+f"(acc[i][j][3])
                        : "r"(af[i][0]), "r"(af[i][1]), "r"(af[i][2]), "r"(af[i][3]),
                          "r"(b0), "r"(b1));
                }
            }
        }
    };

    char* Abuf[2] = { smem, smem + TILE_BYTES };
    char* Bbuf[2] = { smem + 2 * TILE_BYTES, smem + 3 * TILE_BYTES };

    ldcvtA(0); ldcvtB(0);
    stA(Abuf[0]); stB(Bbuf[0]);
    __syncthreads();

    for (int kt = 0; kt < ktiles; kt++) {
        const int cur = kt & 1;
        const bool more = (kt + 1) < ktiles;
        compute(Abuf[cur], Bbuf[cur]);
        if (more) {
            ldcvtA(kt + 1); ldcvtB(kt + 1);
            stA(Abuf[cur ^ 1]); stB(Bbuf[cur ^ 1]);
        }
        __syncthreads();
    }

    const int c2 = cc * 2;
#pragma unroll
    for (int i = 0; i < 4; i++) {
        int row = mtile * BM + wm0 + i * 16 + rr;
#pragma unroll
        for (int j = 0; j < 4; j++) {
            int col = ntile * BN + wn0 + j * 8 + c2;
            size_t o = ((size_t)slab * B_SZ + row) * (size_t)ldc + col;
            *reinterpret_cast<float2*>(&Cp[o]) = make_float2(acc[i][j][0], acc[i][j][1]);
            *reinterpret_cast<float2*>(&Cp[o + 8 * (size_t)ldc]) =
                make_float2(acc[i][j][2], acc[i][j][3]);
        }
    }
}

// ===================== small kernels =====================
__global__ void k_init() {
    g_mm[0] = encf(FLT_MAX); g_mm[1] = encf(-FLT_MAX);
    g_mm[2] = encf(FLT_MAX); g_mm[3] = encf(-FLT_MAX);
}

__global__ void k_minmax(const float4* __restrict__ x, int n4) {
    float lo = FLT_MAX, hi = -FLT_MAX;
    for (int i = blockIdx.x * blockDim.x + threadIdx.x; i < n4; i += gridDim.x * blockDim.x) {
        float4 v = x[i];
        lo = fminf(lo, fminf(fminf(v.x, v.y), fminf(v.z, v.w)));
        hi = fmaxf(hi, fmaxf(fmaxf(v.x, v.y), fmaxf(v.z, v.w)));
    }
#pragma unroll
    for (int o = 16; o; o >>= 1) {
        lo = fminf(lo, __shfl_xor_sync(0xffffffffu, lo, o));
        hi = fmaxf(hi, __shfl_xor_sync(0xffffffffu, hi, o));
    }
    __shared__ float slo[8], shi[8];
    if ((threadIdx.x & 31) == 0) { slo[threadIdx.x >> 5] = lo; shi[threadIdx.x >> 5] = hi; }
    __syncthreads();
    if (threadIdx.x == 0) {
#pragma unroll
        for (int w = 1; w < 8; w++) { lo = fminf(lo, slo[w]); hi = fmaxf(hi, shi[w]); }
        atomicMin(&g_mm[0], encf(lo));
        atomicMax(&g_mm[1], encf(hi));
    }
}

// 512 threads, float2 per thread (2 contiguous columns)
__global__ void k_reduce_ln0(const float* __restrict__ part,
                             const float* __restrict__ gamma,
                             const float* __restrict__ beta) {
    const int b = blockIdx.x, tid = threadIdx.x;
    float2 hv = make_float2(0.f, 0.f);
    for (int s = 0; s < S0_TOT; s++) {
        float2 v = *reinterpret_cast<const float2*>(
            &part[((size_t)s * B_SZ + b) * D1 + tid * 2]);
        hv.x += v.x; hv.y += v.y;
    }
    __shared__ float sbuf[32];
    float mean = blkSum(hv.x + hv.y, sbuf) * (1.0f / D1);
    float dx = hv.x - mean, dy = hv.y - mean;
    float inv = rsqrtf(blkSum(dx * dx + dy * dy, sbuf) * (1.0f / D1) + 1e-5f);
    float2 gv = *reinterpret_cast<const float2*>(&gamma[tid * 2]);
    float2 bv = *reinterpret_cast<const float2*>(&beta[tid * 2]);
    float a0 = silu(dx * inv * gv.x + bv.x);
    float a1 = silu(dy * inv * gv.y + bv.y);
    *reinterpret_cast<float2*>(&g_h0[b * D1 + tid * 2]) = make_float2(a0, a1);
    float lo = fminf(a0, a1), hi = fmaxf(a0, a1);
#pragma unroll
    for (int o = 16; o; o >>= 1) {
        lo = fminf(lo, __shfl_xor_sync(0xffffffffu, lo, o));
        hi = fmaxf(hi, __shfl_xor_sync(0xffffffffu, hi, o));
    }
    __shared__ float slo[16], shi[16];
    if ((tid & 31) == 0) { slo[tid >> 5] = lo; shi[tid >> 5] = hi; }
    __syncthreads();
    if (tid == 0) {
#pragma unroll
        for (int w = 1; w < 16; w++) { lo = fminf(lo, slo[w]); hi = fmaxf(hi, shi[w]); }
        atomicMin(&g_mm[2], encf(lo));
        atomicMax(&g_mm[3], encf(hi));
    }
}

__global__ void k_reduce_ln1(const float* __restrict__ part,
                             const float* __restrict__ gamma,
                             const float* __restrict__ beta,
                             const float* __restrict__ ow,
                             const float* __restrict__ ob,
                             float* __restrict__ out) {
    const int b = blockIdx.x, tid = threadIdx.x;  // 128 threads
    float acc = 0.f;
    for (int s = 0; s < SL1_TOT; s++) acc += part[((size_t)s * B_SZ + b) * D2 + tid];
    __shared__ float sbuf[32];
    float mean = blkSum(acc, sbuf) * (1.0f / D2);
    float d = acc - mean;
    float var = blkSum(d * d, sbuf) * (1.0f / D2);
    float y = d * rsqrtf(var + 1e-5f) * gamma[tid] + beta[tid];
    float a = silu(y);
    float l0 = blkSum(a * ow[tid], sbuf);
    float l1 = blkSum(a * ow[128 + tid], sbuf);
    if (tid == 0) {
        l0 += ob[0]; l1 += ob[1];
        float m = fmaxf(l0, l1);
        float e0 = expf(l0 - m), e1 = expf(l1 - m);
        float inv = 1.f / (e0 + e1);
        out[b * 2 + 0] = e0 * inv;
        out[b * 2 + 1] = e1 * inv;
    }
}

extern "C" void kernel_launch(void* const* d_in, const int* in_sizes, int n_in,
                              void* d_out, int out_size) {
    (void)in_sizes; (void)n_in; (void)out_size;
    const float* x       = (const float*)d_in[0];
    const float* base_w0 = (const float*)d_in[1];
    const float* poly_w0 = (const float*)d_in[2];
    const float* ln_g0   = (const float*)d_in[3];
    const float* ln_b0   = (const float*)d_in[4];
    const float* base_w1 = (const float*)d_in[5];
    const float* poly_w1 = (const float*)d_in[6];
    const float* ln_g1   = (const float*)d_in[7];
    const float* ln_b1   = (const float*)d_in[8];
    const float* out_w   = (const float*)d_in[9];
    const float* out_b   = (const float*)d_in[10];
    float* out = (float*)d_out;

    float *part0, *part1, *h0;
    cudaGetSymbolAddress((void**)&part0, g_part0);
    cudaGetSymbolAddress((void**)&part1, g_part1);
    cudaGetSymbolAddress((void**)&h0, g_h0);

    cudaFuncSetAttribute(kal_l0, cudaFuncAttributeMaxDynamicSharedMemorySize, SMEM_WS);
    cudaFuncSetAttribute(kal_gemm_bs<0>, cudaFuncAttributeMaxDynamicSharedMemorySize, SMEM_BS);
    cudaFuncSetAttribute(kal_gemm_bs<1>, cudaFuncAttributeMaxDynamicSharedMemorySize, SMEM_BS);

    k_init<<<1, 1>>>();
    k_minmax<<<1024, 256>>>((const float4*)x, B_SZ * D0 / 4);

    // layer 0: single merged launch; poly CTAs (z<64) first, base CTAs backfill
    kal_l0<<<dim3(8, 2, S0_TOT), NT_WS, SMEM_WS>>>(x, base_w0, poly_w0, part0);
    k_reduce_ln0<<<B_SZ, 512>>>(part0, ln_g0, ln_b0);

    // layer 1 (small): bulk-sync
    kal_gemm_bs<0><<<dim3(1, 2, S3), NT_BS, SMEM_BS>>>(h0, D1, base_w1, D1,
                                                       part1, D2, KT3, 2);
    kal_gemm_bs<1><<<dim3(1, 2, S4), NT_BS, SMEM_BS>>>(h0, D1, poly_w1, (long)D1 * 4,
                                                       part1 + (size_t)S3 * B_SZ * D2,
                                                       D2, KT4, 2);
    k_reduce_ln1<<<B_SZ, 128>>>(part1, ln_g1, ln_b1, out_w, out_b, out);
}

// round 16
// speedup vs baseline: 1.0539x; 1.0041x over previous
#include <cuda_runtime.h>
#include <cuda_fp16.h>
#include <math.h>
#include <float.h>
#include <stdint.h>

#define B_SZ 256
#define D0 50176
#define D1 1024
#define D2 128
#define BM 128
#define BN 128
#define BK 64               // layer-1 bulk-sync K fp16 per tile
#define BKW 128             // ws K fp16 per stage (two 64-elem halves)

#define NT_BS 256
#define NT_WS 512           // 8 consumer warps + 8 producer warps
#define STAGES 3

// layer0 merged grid (BKW=128 units): poly 56 slabs x 28 kt [z 0..55];
//                                     base 28 slabs x 14 kt [z 56..83]
#define S2 56
#define KT2 28
#define S1 28
#define KT1 14
#define S0_TOT (S2 + S1)    // 84
// layer1 (bulk-sync, BK=64 units)
#define S3 8
#define KT3 2
#define S4 16
#define KT4 4
#define SL1_TOT (S3 + S4)

#define SUB_TILE 16384          // 128 rows x 128B (64 fp16)
#define TILE_WS 32768           // A or B per stage: lo|hi sub-tiles
#define STAGE_BYTES (2 * TILE_WS)
#define SOFF_TILE 1024
#define SMEM_WS (SOFF_TILE + STAGES * STAGE_BYTES)  // 197632
#define TILE_BS 16384
#define SMEM_BS (4 * TILE_BS)

__device__ float    g_part0[(size_t)S0_TOT * B_SZ * D1];
__device__ float    g_part1[(size_t)SL1_TOT * B_SZ * D2];
__device__ float    g_h0[B_SZ * D1];
__device__ unsigned g_mm[4];

__device__ __forceinline__ unsigned encf(float f) {
    unsigned u = __float_as_uint(f);
    return (u & 0x80000000u) ? ~u : (u | 0x80000000u);
}
__device__ __forceinline__ float decf(unsigned u) {
    u = (u & 0x80000000u) ? (u & 0x7FFFFFFFu) : ~u;
    return __uint_as_float(u);
}
__device__ __forceinline__ uint32_t pack2(float a, float b) {
    __half2 h = __floats2half2_rn(a, b);
    return *reinterpret_cast<uint32_t*>(&h);
}
__device__ __forceinline__ float silu(float a) {
    return __fdividef(a, 1.0f + __expf(-a));
}
__device__ __forceinline__ uint32_t smem_u32(const void* p) {
    uint32_t a;
    asm("{ .reg .u64 t; cvta.to.shared.u64 t, %1; cvt.u32.u64 %0, t; }" : "=r"(a) : "l"(p));
    return a;
}
__device__ __forceinline__ void mbar_init(uint32_t m, uint32_t cnt) {
    asm volatile("mbarrier.init.shared.b64 [%0], %1;" :: "r"(m), "r"(cnt) : "memory");
}
__device__ __forceinline__ void mbar_arrive(uint32_t m) {
    asm volatile("mbarrier.arrive.shared.b64 _, [%0];" :: "r"(m) : "memory");
}
__device__ __forceinline__ void mbar_wait(uint32_t m, uint32_t ph) {
    uint32_t done;
    asm volatile("{\n\t.reg .pred p;\n\t"
                 "mbarrier.try_wait.parity.acquire.cta.shared::cta.b64 p, [%1], %2;\n\t"
                 "selp.b32 %0, 1, 0, p;\n\t}"
                 : "=r"(done) : "r"(m), "r"(ph) : "memory");
    if (!done) {
        asm volatile("{\n\t.reg .pred P1;\n\t"
                     "WL_%=:\n\t"
                     "mbarrier.try_wait.parity.acquire.cta.shared::cta.b64 P1, [%0], %1, 0x989680;\n\t"
                     "@P1 bra.uni WD_%=;\n\t"
                     "bra.uni WL_%=;\n\t"
                     "WD_%=:\n\t}"
                     :: "r"(m), "r"(ph) : "memory");
    }
}
__device__ __forceinline__ float blkSum(float v, float* sbuf) {
    int lane = threadIdx.x & 31;
#pragma unroll
    for (int o = 16; o; o >>= 1) v += __shfl_xor_sync(0xffffffffu, v, o);
    __syncthreads();
    if (lane == 0) sbuf[threadIdx.x >> 5] = v;
    __syncthreads();
    int nw = blockDim.x >> 5;
    float r = (lane < nw) ? sbuf[lane] : 0.f;
#pragma unroll
    for (int o = 16; o; o >>= 1) r += __shfl_xor_sync(0xffffffffu, r, o);
    return r;
}

// ---- producer fill loop, fully specialized per MODE (compile-time strides) ----
// Each kt covers BKW=128 fp16 K-elements, stored as two 16KB sub-tiles (kh=0,1).
template <int MODE>
__device__ __forceinline__ void l0_produce(
    const float* __restrict__ A, const float* __restrict__ W,
    char* smem, uint32_t sb, int ntile, int mtile, long kbase, int ktiles, int ptid)
{
    const int rowg = ptid >> 3, sub = ptid & 7;
    constexpr long LDW = MODE ? (long)D0 * 4 : (long)D0;

    const float* asrc;
    float sA = 0.f, sBc = 0.f;
    if (MODE == 0) {
        asrc = A + (size_t)(mtile * BM + rowg) * D0 + kbase + sub * 8;
    } else {
        asrc = A + (size_t)(mtile * BM + rowg) * D0 + (kbase >> 2) + sub * 2;
        float xmin = decf(g_mm[0]), xmax = decf(g_mm[1]);
        sA = 2.0f / (xmax - xmin);
        sBc = -sA * xmin - 1.0f;
    }
    const float* wsrc = W + (size_t)(ntile * BN + rowg) * LDW + kbase + sub * 8;

    uint32_t soff[4];
#pragma unroll
    for (int g = 0; g < 4; g++) {
        int r = rowg + g * 32;
        soff[g] = r * 128 + ((sub ^ (r & 7)) << 4);
    }

    int st = 0, ph = 1;
    for (int kt = 0; kt < ktiles; kt++) {
        mbar_wait(sb + st * 16 + 8, ph);
        char* ab = smem + SOFF_TILE + st * STAGE_BYTES;
        char* bb = ab + TILE_WS;
#pragma unroll
        for (int kh = 0; kh < 2; kh++) {
            const long ko = (long)kt * BKW + kh * 64;
#pragma unroll
            for (int g = 0; g < 4; g++) {
                const float* p = wsrc + (size_t)g * 32 * LDW + ko;
                float4 w0 = *reinterpret_cast<const float4*>(p);
                float4 w1 = *reinterpret_cast<const float4*>(p + 4);
                *reinterpret_cast<uint4*>(bb + kh * SUB_TILE + soff[g]) =
                    make_uint4(pack2(w0.x, w0.y), pack2(w0.z, w0.w),
                               pack2(w1.x, w1.y), pack2(w1.z, w1.w));
            }
            if (MODE == 0) {
#pragma unroll
                for (int g = 0; g < 4; g++) {
                    const float* p = asrc + (size_t)g * 32 * D0 + ko;
                    float4 a0 = *reinterpret_cast<const float4*>(p);
                    float4 a1 = *reinterpret_cast<const float4*>(p + 4);
                    *reinterpret_cast<uint4*>(ab + kh * SUB_TILE + soff[g]) =
                        make_uint4(pack2(silu(a0.x), silu(a0.y)),
                                   pack2(silu(a0.z), silu(a0.w)),
                                   pack2(silu(a1.x), silu(a1.y)),
                                   pack2(silu(a1.z), silu(a1.w)));
                }
            } else {
#pragma unroll
                for (int g = 0; g < 4; g++) {
                    float2 xv = *reinterpret_cast<const float2*>(
                        asrc + (size_t)g * 32 * D0 + kt * 32 + kh * 16);
                    float t0 = fmaf(xv.x, sA, sBc), t1 = fmaf(xv.y, sA, sBc);
                    float q0 = t0 * t0, q1 = t1 * t1;
                    *reinterpret_cast<uint4*>(ab + kh * SUB_TILE + soff[g]) = make_uint4(
                        pack2(1.0f, t0),
                        pack2(fmaf(1.5f, q0, -0.5f), t0 * fmaf(2.5f, q0, -1.5f)),
                        pack2(1.0f, t1),
                        pack2(fmaf(1.5f, q1, -0.5f), t1 * fmaf(2.5f, q1, -1.5f)));
                }
            }
        }
        mbar_arrive(sb + st * 16);
        if (++st == STAGES) { st = 0; ph ^= 1; }
    }
}

// ===================== merged layer-0 warp-specialized GEMM =====================
// z < S2: poly slab z (28 kt128); z >= S2: base slab z-S2 (14 kt128).
__global__ void __launch_bounds__(NT_WS, 1) kal_l0(
    const float* __restrict__ A,
    const float* __restrict__ BW, const float* __restrict__ PW,
    float* __restrict__ Cp)
{
    extern __shared__ char smem[];
    const uint32_t sb = smem_u32(smem);
    const int tid = threadIdx.x, lane = tid & 31, wid = tid >> 5;
    const int ntile = blockIdx.x, mtile = blockIdx.y, z = blockIdx.z;
    const int mode1 = (z < S2);
    const int ktiles = mode1 ? KT2 : KT1;

    if (tid == 0) {
#pragma unroll
        for (int s = 0; s < STAGES; s++) {
            mbar_init(sb + s * 16, 256);      // full
            mbar_init(sb + s * 16 + 8, 256);  // empty
        }
    }
    __syncthreads();

    if (wid >= 8) {
        if (mode1)
            l0_produce<1>(A, PW, smem, sb, ntile, mtile, (long)z * KT2 * BKW, KT2, tid - 256);
        else
            l0_produce<0>(A, BW, smem, sb, ntile, mtile, (long)(z - S2) * KT1 * BKW, KT1, tid - 256);
    } else {
        // ---- consumer (8 warps, 64x32 tiles), MODE-independent ----
        const int wm0 = (wid & 1) * 64, wn0 = (wid >> 1) * 32;
        const int rr = lane >> 2, cc = lane & 3;
        const int h7 = lane & 7;
        const int a_row = (lane & 15);
        const int a_hi = lane >> 4;
        const int b_rowoff = ((lane >> 4) << 3) + h7;
        const int b_hi = (lane >> 3) & 1;

        float acc[4][4][4] = {};

        int st = 0, ph = 0;
        for (int kt = 0; kt < ktiles; kt++) {
            mbar_wait(sb + st * 16, ph);
            const uint32_t abase0 = sb + SOFF_TILE + st * STAGE_BYTES;
            const uint32_t bbase0 = abase0 + TILE_WS;
#pragma unroll
            for (int kc = 0; kc < 8; kc++) {
                const uint32_t abase = abase0 + (kc >> 2) * SUB_TILE;
                const uint32_t bbase = bbase0 + (kc >> 2) * SUB_TILE;
                const int kk = kc & 3;
                unsigned af[4][4];
#pragma unroll
                for (int i = 0; i < 4; i++) {
                    uint32_t addr = abase + (wm0 + i * 16 + a_row) * 128 +
                                    (((2 * kk + a_hi) ^ h7) << 4);
                    asm volatile(
                        "ldmatrix.sync.aligned.m8n8.x4.shared.b16 {%0,%1,%2,%3}, [%4];"
                        : "=r"(af[i][0]), "=r"(af[i][1]), "=r"(af[i][2]), "=r"(af[i][3])
                        : "r"(addr));
                }
                unsigned bfr[8];
#pragma unroll
                for (int jj = 0; jj < 2; jj++) {
                    uint32_t addr = bbase + (wn0 + jj * 16 + b_rowoff) * 128 +
                                    (((2 * kk + b_hi) ^ h7) << 4);
                    asm volatile(
                        "ldmatrix.sync.aligned.m8n8.x4.shared.b16 {%0,%1,%2,%3}, [%4];"
                        : "=r"(bfr[jj * 4]), "=r"(bfr[jj * 4 + 1]),
                          "=r"(bfr[jj * 4 + 2]), "=r"(bfr[jj * 4 + 3])
                        : "r"(addr));
                }
#pragma unroll
                for (int j = 0; j < 4; j++) {
                    unsigned b0 = bfr[(j >> 1) * 4 + (j & 1) * 2];
                    unsigned b1 = bfr[(j >> 1) * 4 + (j & 1) * 2 + 1];
#pragma unroll
                    for (int i = 0; i < 4; i++) {
                        asm volatile(
                            "mma.sync.aligned.m16n8k16.row.col.f32.f16.f16.f32 "
                            "{%0,%1,%2,%3}, {%4,%5,%6,%7}, {%8,%9}, {%0,%1,%2,%3};"
                            : "+f"(acc[i][j][0]), "+f"(acc[i][j][1]),
                              "+f"(acc[i][j][2]), "+f"(acc[i][j][3])
                            : "r"(af[i][0]), "r"(af[i][1]), "r"(af[i][2]), "r"(af[i][3]),
                              "r"(b0), "r"(b1));
                    }
                }
            }
            mbar_arrive(sb + st * 16 + 8);
            if (++st == STAGES) { st = 0; ph ^= 1; }
        }

        const int c2 = cc * 2;
#pragma unroll
        for (int i = 0; i < 4; i++) {
            int row = mtile * BM + wm0 + i * 16 + rr;
#pragma unroll
            for (int j = 0; j < 4; j++) {
                int col = ntile * BN + wn0 + j * 8 + c2;
                size_t o = ((size_t)z * B_SZ + row) * (size_t)D1 + col;
                *reinterpret_cast<float2*>(&Cp[o]) = make_float2(acc[i][j][0], acc[i][j][1]);
                *reinterpret_cast<float2*>(&Cp[o + 8 * (size_t)D1]) =
                    make_float2(acc[i][j][2], acc[i][j][3]);
            }
        }
    }
}

// ===================== bulk-sync fp16 GEMM (layer-1, small, BK=64) =====================
template <int MODE>
__global__ void __launch_bounds__(NT_BS, 2) kal_gemm_bs(
    const float* __restrict__ A, int lda,
    const float* __restrict__ W, long ldw,
    float* __restrict__ Cp, int ldc, int ktiles, int mmOff)
{
    extern __shared__ char smem[];
    const int tid = threadIdx.x, lane = tid & 31, wid = tid >> 5;
    const int wm0 = (wid & 1) * 64, wn0 = (wid >> 1) * 32;
    const int rr = lane >> 2, cc = lane & 3;
    const int ntile = blockIdx.x, mtile = blockIdx.y, slab = blockIdx.z;
    const long kbase = (long)slab * ktiles * BK;

    const int rowg = tid >> 3, sub = tid & 7;
    const int h7 = lane & 7;
    const int a_row = (lane & 15);
    const int a_hi = lane >> 4;
    const int b_rowoff = ((lane >> 4) << 3) + h7;
    const int b_hi = (lane >> 3) & 1;

    const float* asrc;
    float sA = 0.f, sBc = 0.f;
    if (MODE == 0) {
        asrc = A + (size_t)(mtile * BM + rowg) * lda + kbase + sub * 8;
    } else {
        asrc = A + (size_t)(mtile * BM + rowg) * lda + (kbase >> 2) + sub * 2;
        float xmin = decf(g_mm[mmOff]), xmax = decf(g_mm[mmOff + 1]);
        sA = 2.0f / (xmax - xmin);
        sBc = -sA * xmin - 1.0f;
    }
    const float* wsrc = W + (size_t)(ntile * BN + rowg) * ldw + kbase + sub * 8;

    uint32_t soff[4];
#pragma unroll
    for (int g = 0; g < 4; g++) {
        int r = rowg + g * 32;
        soff[g] = r * 128 + ((sub ^ (r & 7)) << 4);
    }

    uint4 aS[4], bS[4];

    auto ldcvtB = [&](int kt) {
#pragma unroll
        for (int g = 0; g < 4; g++) {
            const float* p = wsrc + (size_t)g * 32 * ldw + (size_t)kt * BK;
            float4 w0 = *reinterpret_cast<const float4*>(p);
            float4 w1 = *reinterpret_cast<const float4*>(p + 4);
            bS[g] = make_uint4(pack2(w0.x, w0.y), pack2(w0.z, w0.w),
                               pack2(w1.x, w1.y), pack2(w1.z, w1.w));
        }
    };
    auto ldcvtA = [&](int kt) {
        if (MODE == 0) {
#pragma unroll
            for (int g = 0; g < 4; g++) {
                const float* p = asrc + (size_t)g * 32 * lda + (size_t)kt * BK;
                float4 a0 = *reinterpret_cast<const float4*>(p);
                float4 a1 = *reinterpret_cast<const float4*>(p + 4);
                aS[g] = make_uint4(pack2(silu(a0.x), silu(a0.y)),
                                   pack2(silu(a0.z), silu(a0.w)),
                                   pack2(silu(a1.x), silu(a1.y)),
                                   pack2(silu(a1.z), silu(a1.w)));
            }
        } else {
#pragma unroll
            for (int g = 0; g < 4; g++) {
                float2 xv = *reinterpret_cast<const float2*>(
                    asrc + (size_t)g * 32 * lda + kt * 16);
                float t0 = fmaf(xv.x, sA, sBc), t1 = fmaf(xv.y, sA, sBc);
                float q0 = t0 * t0, q1 = t1 * t1;
                aS[g] = make_uint4(
                    pack2(1.0f, t0),
                    pack2(fmaf(1.5f, q0, -0.5f), t0 * fmaf(2.5f, q0, -1.5f)),
                    pack2(1.0f, t1),
                    pack2(fmaf(1.5f, q1, -0.5f), t1 * fmaf(2.5f, q1, -1.5f)));
            }
        }
    };
    auto stA = [&](char* ast) {
#pragma unroll
        for (int g = 0; g < 4; g++) *reinterpret_cast<uint4*>(ast + soff[g]) = aS[g];
    };
    auto stB = [&](char* bst) {
#pragma unroll
        for (int g = 0; g < 4; g++) *reinterpret_cast<uint4*>(bst + soff[g]) = bS[g];
    };

    float acc[4][4][4] = {};

    auto compute = [&](const char* Ast, const char* Bst) {
        const uint32_t abase = (uint32_t)__cvta_generic_to_shared(Ast);
        const uint32_t bbase = (uint32_t)__cvta_generic_to_shared(Bst);
#pragma unroll
        for (int kc = 0; kc < 4; kc++) {
            unsigned af[4][4];
#pragma unroll
            for (int i = 0; i < 4; i++) {
                uint32_t addr = abase + (wm0 + i * 16 + a_row) * 128 +
                                (((2 * kc + a_hi) ^ h7) << 4);
                asm volatile(
                    "ldmatrix.sync.aligned.m8n8.x4.shared.b16 {%0,%1,%2,%3}, [%4];"
                    : "=r"(af[i][0]), "=r"(af[i][1]), "=r"(af[i][2]), "=r"(af[i][3])
                    : "r"(addr));
            }
            unsigned bfr[8];
#pragma unroll
            for (int jj = 0; jj < 2; jj++) {
                uint32_t addr = bbase + (wn0 + jj * 16 + b_rowoff) * 128 +
                                (((2 * kc + b_hi) ^ h7) << 4);
                asm volatile(
                    "ldmatrix.sync.aligned.m8n8.x4.shared.b16 {%0,%1,%2,%3}, [%4];"
                    : "=r"(bfr[jj * 4]), "=r"(bfr[jj * 4 + 1]),
                      "=r"(bfr[jj * 4 + 2]), "=r"(bfr[jj * 4 + 3])
                    : "r"(addr));
            }
#pragma unroll
            for (int j = 0; j < 4; j++) {
                unsigned b0 = bfr[(j >> 1) * 4 + (j & 1) * 2];
                unsigned b1 = bfr[(j >> 1) * 4 + (j & 1) * 2 + 1];
#pragma unroll
                for (int i = 0; i < 4; i++) {
                    asm volatile(
                        "mma.sync.aligned.m16n8k16.row.col.f32.f16.f16.f32 "
                        "{%0,%1,%2,%3}, {%4,%5,%6,%7}, {%8,%9}, {%0,%1,%2,%3};"
                        : "+f"(acc[i][j][0]), "+f"(acc[i][j][1]),
                          "+f"(acc[i][j][2]), "+f"(acc[i][j][3])
                        : "r"(af[i][0]), "r"(af[i][1]), "r"(af[i][2]), "r"(af[i][3]),
                          "r"(b0), "r"(b1));
                }
            }
        }
    };

    char* Abuf[2] = { smem, smem + TILE_BS };
    char* Bbuf[2] = { smem + 2 * TILE_BS, smem + 3 * TILE_BS };

    ldcvtA(0); ldcvtB(0);
    stA(Abuf[0]); stB(Bbuf[0]);
    __syncthreads();

    for (int kt = 0; kt < ktiles; kt++) {
        const int cur = kt & 1;
        const bool more = (kt + 1) < ktiles;
        compute(Abuf[cur], Bbuf[cur]);
        if (more) {
            ldcvtA(kt + 1); ldcvtB(kt + 1);
            stA(Abuf[cur ^ 1]); stB(Bbuf[cur ^ 1]);
        }
        __syncthreads();
    }

    const int c2 = cc * 2;
#pragma unroll
    for (int i = 0; i < 4; i++) {
        int row = mtile * BM + wm0 + i * 16 + rr;
#pragma unroll
        for (int j = 0; j < 4; j++) {
            int col = ntile * BN + wn0 + j * 8 + c2;
            size_t o = ((size_t)slab * B_SZ + row) * (size_t)ldc + col;
            *reinterpret_cast<float2*>(&Cp[o]) = make_float2(acc[i][j][0], acc[i][j][1]);
            *reinterpret_cast<float2*>(&Cp[o + 8 * (size_t)ldc]) =
                make_float2(acc[i][j][2], acc[i][j][3]);
        }
    }
}

// ===================== small kernels =====================
__global__ void k_init() {
    g_mm[0] = encf(FLT_MAX); g_mm[1] = encf(-FLT_MAX);
    g_mm[2] = encf(FLT_MAX); g_mm[3] = encf(-FLT_MAX);
}

__global__ void k_minmax(const float4* __restrict__ x, int n4) {
    float lo = FLT_MAX, hi = -FLT_MAX;
    for (int i = blockIdx.x * blockDim.x + threadIdx.x; i < n4; i += gridDim.x * blockDim.x) {
        float4 v = x[i];
        lo = fminf(lo, fminf(fminf(v.x, v.y), fminf(v.z, v.w)));
        hi = fmaxf(hi, fmaxf(fmaxf(v.x, v.y), fmaxf(v.z, v.w)));
    }
#pragma unroll
    for (int o = 16; o; o >>= 1) {
        lo = fminf(lo, __shfl_xor_sync(0xffffffffu, lo, o));
        hi = fmaxf(hi, __shfl_xor_sync(0xffffffffu, hi, o));
    }
    __shared__ float slo[8], shi[8];
    if ((threadIdx.x & 31) == 0) { slo[threadIdx.x >> 5] = lo; shi[threadIdx.x >> 5] = hi; }
    __syncthreads();
    if (threadIdx.x == 0) {
#pragma unroll
        for (int w = 1; w < 8; w++) { lo = fminf(lo, slo[w]); hi = fmaxf(hi, shi[w]); }
        atomicMin(&g_mm[0], encf(lo));
        atomicMax(&g_mm[1], encf(hi));
    }
}

// 512 threads, float2 per thread (2 contiguous columns)
__global__ void k_reduce_ln0(const float* __restrict__ part,
                             const float* __restrict__ gamma,
                             const float* __restrict__ beta) {
    const int b = blockIdx.x, tid = threadIdx.x;
    float2 hv = make_float2(0.f, 0.f);
    for (int s = 0; s < S0_TOT; s++) {
        float2 v = *reinterpret_cast<const float2*>(
            &part[((size_t)s * B_SZ + b) * D1 + tid * 2]);
        hv.x += v.x; hv.y += v.y;
    }
    __shared__ float sbuf[32];
    float mean = blkSum(hv.x + hv.y, sbuf) * (1.0f / D1);
    float dx = hv.x - mean, dy = hv.y - mean;
    float inv = rsqrtf(blkSum(dx * dx + dy * dy, sbuf) * (1.0f / D1) + 1e-5f);
    float2 gv = *reinterpret_cast<const float2*>(&gamma[tid * 2]);
    float2 bv = *reinterpret_cast<const float2*>(&beta[tid * 2]);
    float a0 = silu(dx * inv * gv.x + bv.x);
    float a1 = silu(dy * inv * gv.y + bv.y);
    *reinterpret_cast<float2*>(&g_h0[b * D1 + tid * 2]) = make_float2(a0, a1);
    float lo = fminf(a0, a1), hi = fmaxf(a0, a1);
#pragma unroll
    for (int o = 16; o; o >>= 1) {
        lo = fminf(lo, __shfl_xor_sync(0xffffffffu, lo, o));
        hi = fmaxf(hi, __shfl_xor_sync(0xffffffffu, hi, o));
    }
    __shared__ float slo[16], shi[16];
    if ((tid & 31) == 0) { slo[tid >> 5] = lo; shi[tid >> 5] = hi; }
    __syncthreads();
    if (tid == 0) {
#pragma unroll
        for (int w = 1; w < 16; w++) { lo = fminf(lo, slo[w]); hi = fmaxf(hi, shi[w]); }
        atomicMin(&g_mm[2], encf(lo));
        atomicMax(&g_mm[3], encf(hi));
    }
}

__global__ void k_reduce_ln1(const float* __restrict__ part,
                             const float* __restrict__ gamma,
                             const float* __restrict__ beta,
                             const float* __restrict__ ow,
                             const float* __restrict__ ob,
                             float* __restrict__ out) {
    const int b = blockIdx.x, tid = threadIdx.x;  // 128 threads
    float acc = 0.f;
    for (int s = 0; s < SL1_TOT; s++) acc += part[((size_t)s * B_SZ + b) * D2 + tid];
    __shared__ float sbuf[32];
    float mean = blkSum(acc, sbuf) * (1.0f / D2);
    float d = acc - mean;
    float var = blkSum(d * d, sbuf) * (1.0f / D2);
    float y = d * rsqrtf(var + 1e-5f) * gamma[tid] + beta[tid];
    float a = silu(y);
    float l0 = blkSum(a * ow[tid], sbuf);
    float l1 = blkSum(a * ow[128 + tid], sbuf);
    if (tid == 0) {
        l0 += ob[0]; l1 += ob[1];
        float m = fmaxf(l0, l1);
        float e0 = expf(l0 - m), e1 = expf(l1 - m);
        float inv = 1.f / (e0 + e1);
        out[b * 2 + 0] = e0 * inv;
        out[b * 2 + 1] = e1 * inv;
    }
}

extern "C" void kernel_launch(void* const* d_in, const int* in_sizes, int n_in,
                              void* d_out, int out_size) {
    (void)in_sizes; (void)n_in; (void)out_size;
    const float* x       = (const float*)d_in[0];
    const float* base_w0 = (const float*)d_in[1];
    const float* poly_w0 = (const float*)d_in[2];
    const float* ln_g0   = (const float*)d_in[3];
    const float* ln_b0   = (const float*)d_in[4];
    const float* base_w1 = (const float*)d_in[5];
    const float* poly_w1 = (const float*)d_in[6];
    const float* ln_g1   = (const float*)d_in[7];
    const float* ln_b1   = (const float*)d_in[8];
    const float* out_w   = (const float*)d_in[9];
    const float* out_b   = (const float*)d_in[10];
    float* out = (float*)d_out;

    float *part0, *part1, *h0;
    cudaGetSymbolAddress((void**)&part0, g_part0);
    cudaGetSymbolAddress((void**)&part1, g_part1);
    cudaGetSymbolAddress((void**)&h0, g_h0);

    cudaFuncSetAttribute(kal_l0, cudaFuncAttributeMaxDynamicSharedMemorySize, SMEM_WS);
    cudaFuncSetAttribute(kal_gemm_bs<0>, cudaFuncAttributeMaxDynamicSharedMemorySize, SMEM_BS);
    cudaFuncSetAttribute(kal_gemm_bs<1>, cudaFuncAttributeMaxDynamicSharedMemorySize, SMEM_BS);

    k_init<<<1, 1>>>();
    k_minmax<<<1024, 256>>>((const float4*)x, B_SZ * D0 / 4);

    // layer 0: single merged launch; poly CTAs (z<56) first, base CTAs backfill
    kal_l0<<<dim3(8, 2, S0_TOT), NT_WS, SMEM_WS>>>(x, base_w0, poly_w0, part0);
    k_reduce_ln0<<<B_SZ, 512>>>(part0, ln_g0, ln_b0);

    // layer 1 (small): bulk-sync
    kal_gemm_bs<0><<<dim3(1, 2, S3), NT_BS, SMEM_BS>>>(h0, D1, base_w1, D1,
                                                       part1, D2, KT3, 2);
    kal_gemm_bs<1><<<dim3(1, 2, S4), NT_BS, SMEM_BS>>>(h0, D1, poly_w1, (long)D1 * 4,
                                                       part1 + (size_t)S3 * B_SZ * D2,
                                                       D2, KT4, 2);
    k_reduce_ln1<<<B_SZ, 128>>>(part1, ln_g1, ln_b1, out_w, out_b, out);
}

// round 17
// speedup vs baseline: 1.0669x; 1.0123x over previous
#include <cuda_runtime.h>
#include <cuda_fp16.h>
#include <math.h>
#include <float.h>
#include <stdint.h>

#define B_SZ 256
#define D0 50176
#define D1 1024
#define D2 128
#define BM 128
#define BN 128
#define BK 64               // layer-1 K fp16 per tile
#define BKW 128             // l0 ws K fp16 per stage (two 64-elem halves)

#define NT_BS 256
#define NT_WS 512
#define STAGES 3

// layer0 merged grid (BKW=128 units): poly 56 x 28 kt [z 0..55]; base 28 x 14 kt [z 56..83]
#define S2 56
#define KT2 28
#define S1 28
#define KT1 14
#define S0_TOT (S2 + S1)    // 84
// layer1 merged grid (BK=64 units): base 8 x 2 kt [z 0..7]; poly 16 x 4 kt [z 8..23]
#define S3 8
#define KT3 2
#define S4 16
#define KT4 4
#define SL1_TOT (S3 + S4)

#define SUB_TILE 16384
#define TILE_WS 32768
#define STAGE_BYTES (2 * TILE_WS)
#define SOFF_TILE 1024
#define SMEM_WS (SOFF_TILE + STAGES * STAGE_BYTES)
#define TILE_BS 16384
#define SMEM_BS (4 * TILE_BS)

__device__ float    g_part0[(size_t)S0_TOT * B_SZ * D1];
__device__ float    g_part1[(size_t)SL1_TOT * B_SZ * D2];
__device__ float    g_h0[B_SZ * D1];
__device__ unsigned g_mm[4];

__device__ __forceinline__ unsigned encf(float f) {
    unsigned u = __float_as_uint(f);
    return (u & 0x80000000u) ? ~u : (u | 0x80000000u);
}
__device__ __forceinline__ float decf(unsigned u) {
    u = (u & 0x80000000u) ? (u & 0x7FFFFFFFu) : ~u;
    return __uint_as_float(u);
}
__device__ __forceinline__ uint32_t pack2(float a, float b) {
    __half2 h = __floats2half2_rn(a, b);
    return *reinterpret_cast<uint32_t*>(&h);
}
__device__ __forceinline__ float silu(float a) {
    return __fdividef(a, 1.0f + __expf(-a));
}
__device__ __forceinline__ uint32_t smem_u32(const void* p) {
    uint32_t a;
    asm("{ .reg .u64 t; cvta.to.shared.u64 t, %1; cvt.u32.u64 %0, t; }" : "=r"(a) : "l"(p));
    return a;
}
__device__ __forceinline__ void mbar_init(uint32_t m, uint32_t cnt) {
    asm volatile("mbarrier.init.shared.b64 [%0], %1;" :: "r"(m), "r"(cnt) : "memory");
}
__device__ __forceinline__ void mbar_arrive(uint32_t m) {
    asm volatile("mbarrier.arrive.shared.b64 _, [%0];" :: "r"(m) : "memory");
}
__device__ __forceinline__ void mbar_wait(uint32_t m, uint32_t ph) {
    uint32_t done;
    asm volatile("{\n\t.reg .pred p;\n\t"
                 "mbarrier.try_wait.parity.acquire.cta.shared::cta.b64 p, [%1], %2;\n\t"
                 "selp.b32 %0, 1, 0, p;\n\t}"
                 : "=r"(done) : "r"(m), "r"(ph) : "memory");
    if (!done) {
        asm volatile("{\n\t.reg .pred P1;\n\t"
                     "WL_%=:\n\t"
                     "mbarrier.try_wait.parity.acquire.cta.shared::cta.b64 P1, [%0], %1, 0x989680;\n\t"
                     "@P1 bra.uni WD_%=;\n\t"
                     "bra.uni WL_%=;\n\t"
                     "WD_%=:\n\t}"
                     :: "r"(m), "r"(ph) : "memory");
    }
}
__device__ __forceinline__ float blkSum(float v, float* sbuf) {
    int lane = threadIdx.x & 31;
#pragma unroll
    for (int o = 16; o; o >>= 1) v += __shfl_xor_sync(0xffffffffu, v, o);
    __syncthreads();
    if (lane == 0) sbuf[threadIdx.x >> 5] = v;
    __syncthreads();
    int nw = blockDim.x >> 5;
    float r = (lane < nw) ? sbuf[lane] : 0.f;
#pragma unroll
    for (int o = 16; o; o >>= 1) r += __shfl_xor_sync(0xffffffffu, r, o);
    return r;
}

// ---- l0 producer fill loop, compile-time MODE ----
template <int MODE>
__device__ __forceinline__ void l0_produce(
    const float* __restrict__ A, const float* __restrict__ W,
    char* smem, uint32_t sb, int ntile, int mtile, long kbase, int ktiles, int ptid)
{
    const int rowg = ptid >> 3, sub = ptid & 7;
    constexpr long LDW = MODE ? (long)D0 * 4 : (long)D0;

    const float* asrc;
    float sA = 0.f, sBc = 0.f;
    if (MODE == 0) {
        asrc = A + (size_t)(mtile * BM + rowg) * D0 + kbase + sub * 8;
    } else {
        asrc = A + (size_t)(mtile * BM + rowg) * D0 + (kbase >> 2) + sub * 2;
        float xmin = decf(g_mm[0]), xmax = decf(g_mm[1]);
        sA = 2.0f / (xmax - xmin);
        sBc = -sA * xmin - 1.0f;
    }
    const float* wsrc = W + (size_t)(ntile * BN + rowg) * LDW + kbase + sub * 8;

    uint32_t soff[4];
#pragma unroll
    for (int g = 0; g < 4; g++) {
        int r = rowg + g * 32;
        soff[g] = r * 128 + ((sub ^ (r & 7)) << 4);
    }

    int st = 0, ph = 1;
    for (int kt = 0; kt < ktiles; kt++) {
        mbar_wait(sb + st * 16 + 8, ph);
        char* ab = smem + SOFF_TILE + st * STAGE_BYTES;
        char* bb = ab + TILE_WS;
#pragma unroll
        for (int kh = 0; kh < 2; kh++) {
            const long ko = (long)kt * BKW + kh * 64;
#pragma unroll
            for (int g = 0; g < 4; g++) {
                const float* p = wsrc + (size_t)g * 32 * LDW + ko;
                float4 w0 = *reinterpret_cast<const float4*>(p);
                float4 w1 = *reinterpret_cast<const float4*>(p + 4);
                *reinterpret_cast<uint4*>(bb + kh * SUB_TILE + soff[g]) =
                    make_uint4(pack2(w0.x, w0.y), pack2(w0.z, w0.w),
                               pack2(w1.x, w1.y), pack2(w1.z, w1.w));
            }
            if (MODE == 0) {
#pragma unroll
                for (int g = 0; g < 4; g++) {
                    const float* p = asrc + (size_t)g * 32 * D0 + ko;
                    float4 a0 = *reinterpret_cast<const float4*>(p);
                    float4 a1 = *reinterpret_cast<const float4*>(p + 4);
                    *reinterpret_cast<uint4*>(ab + kh * SUB_TILE + soff[g]) =
                        make_uint4(pack2(silu(a0.x), silu(a0.y)),
                                   pack2(silu(a0.z), silu(a0.w)),
                                   pack2(silu(a1.x), silu(a1.y)),
                                   pack2(silu(a1.z), silu(a1.w)));
                }
            } else {
#pragma unroll
                for (int g = 0; g < 4; g++) {
                    float2 xv = *reinterpret_cast<const float2*>(
                        asrc + (size_t)g * 32 * D0 + kt * 32 + kh * 16);
                    float t0 = fmaf(xv.x, sA, sBc), t1 = fmaf(xv.y, sA, sBc);
                    float q0 = t0 * t0, q1 = t1 * t1;
                    *reinterpret_cast<uint4*>(ab + kh * SUB_TILE + soff[g]) = make_uint4(
                        pack2(1.0f, t0),
                        pack2(fmaf(1.5f, q0, -0.5f), t0 * fmaf(2.5f, q0, -1.5f)),
                        pack2(1.0f, t1),
                        pack2(fmaf(1.5f, q1, -0.5f), t1 * fmaf(2.5f, q1, -1.5f)));
                }
            }
        }
        mbar_arrive(sb + st * 16);
        if (++st == STAGES) { st = 0; ph ^= 1; }
    }
}

// ===================== merged layer-0 warp-specialized GEMM =====================
__global__ void __launch_bounds__(NT_WS, 1) kal_l0(
    const float* __restrict__ A,
    const float* __restrict__ BW, const float* __restrict__ PW,
    float* __restrict__ Cp)
{
    extern __shared__ char smem[];
    const uint32_t sb = smem_u32(smem);
    const int tid = threadIdx.x, lane = tid & 31, wid = tid >> 5;
    const int ntile = blockIdx.x, mtile = blockIdx.y, z = blockIdx.z;
    const int mode1 = (z < S2);
    const int ktiles = mode1 ? KT2 : KT1;

    if (tid == 0) {
#pragma unroll
        for (int s = 0; s < STAGES; s++) {
            mbar_init(sb + s * 16, 256);
            mbar_init(sb + s * 16 + 8, 256);
        }
    }
    __syncthreads();

    if (wid >= 8) {
        if (mode1)
            l0_produce<1>(A, PW, smem, sb, ntile, mtile, (long)z * KT2 * BKW, KT2, tid - 256);
        else
            l0_produce<0>(A, BW, smem, sb, ntile, mtile, (long)(z - S2) * KT1 * BKW, KT1, tid - 256);
    } else {
        const int wm0 = (wid & 1) * 64, wn0 = (wid >> 1) * 32;
        const int rr = lane >> 2, cc = lane & 3;
        const int h7 = lane & 7;
        const int a_row = (lane & 15);
        const int a_hi = lane >> 4;
        const int b_rowoff = ((lane >> 4) << 3) + h7;
        const int b_hi = (lane >> 3) & 1;

        float acc[4][4][4] = {};

        int st = 0, ph = 0;
        for (int kt = 0; kt < ktiles; kt++) {
            mbar_wait(sb + st * 16, ph);
            const uint32_t abase0 = sb + SOFF_TILE + st * STAGE_BYTES;
            const uint32_t bbase0 = abase0 + TILE_WS;
#pragma unroll
            for (int kc = 0; kc < 8; kc++) {
                const uint32_t abase = abase0 + (kc >> 2) * SUB_TILE;
                const uint32_t bbase = bbase0 + (kc >> 2) * SUB_TILE;
                const int kk = kc & 3;
                unsigned af[4][4];
#pragma unroll
                for (int i = 0; i < 4; i++) {
                    uint32_t addr = abase + (wm0 + i * 16 + a_row) * 128 +
                                    (((2 * kk + a_hi) ^ h7) << 4);
                    asm volatile(
                        "ldmatrix.sync.aligned.m8n8.x4.shared.b16 {%0,%1,%2,%3}, [%4];"
                        : "=r"(af[i][0]), "=r"(af[i][1]), "=r"(af[i][2]), "=r"(af[i][3])
                        : "r"(addr));
                }
                unsigned bfr[8];
#pragma unroll
                for (int jj = 0; jj < 2; jj++) {
                    uint32_t addr = bbase + (wn0 + jj * 16 + b_rowoff) * 128 +
                                    (((2 * kk + b_hi) ^ h7) << 4);
                    asm volatile(
                        "ldmatrix.sync.aligned.m8n8.x4.shared.b16 {%0,%1,%2,%3}, [%4];"
                        : "=r"(bfr[jj * 4]), "=r"(bfr[jj * 4 + 1]),
                          "=r"(bfr[jj * 4 + 2]), "=r"(bfr[jj * 4 + 3])
                        : "r"(addr));
                }
#pragma unroll
                for (int j = 0; j < 4; j++) {
                    unsigned b0 = bfr[(j >> 1) * 4 + (j & 1) * 2];
                    unsigned b1 = bfr[(j >> 1) * 4 + (j & 1) * 2 + 1];
#pragma unroll
                    for (int i = 0; i < 4; i++) {
                        asm volatile(
                            "mma.sync.aligned.m16n8k16.row.col.f32.f16.f16.f32 "
                            "{%0,%1,%2,%3}, {%4,%5,%6,%7}, {%8,%9}, {%0,%1,%2,%3};"
                            : "+f"(acc[i][j][0]), "+f"(acc[i][j][1]),
                              "+f"(acc[i][j][2]), "+f"(acc[i][j][3])
                            : "r"(af[i][0]), "r"(af[i][1]), "r"(af[i][2]), "r"(af[i][3]),
                              "r"(b0), "r"(b1));
                    }
                }
            }
            mbar_arrive(sb + st * 16 + 8);
            if (++st == STAGES) { st = 0; ph ^= 1; }
        }

        const int c2 = cc * 2;
#pragma unroll
        for (int i = 0; i < 4; i++) {
            int row = mtile * BM + wm0 + i * 16 + rr;
#pragma unroll
            for (int j = 0; j < 4; j++) {
                int col = ntile * BN + wn0 + j * 8 + c2;
                size_t o = ((size_t)z * B_SZ + row) * (size_t)D1 + col;
                *reinterpret_cast<float2*>(&Cp[o]) = make_float2(acc[i][j][0], acc[i][j][1]);
                *reinterpret_cast<float2*>(&Cp[o + 8 * (size_t)D1]) =
                    make_float2(acc[i][j][2], acc[i][j][3]);
            }
        }
    }
}

// ===================== layer-1 bulk-sync body (compile-time MODE) =====================
template <int MODE>
__device__ __forceinline__ void l1_body(
    const float* __restrict__ A, const float* __restrict__ W, long ldw,
    float* __restrict__ Cp, int ktiles, int slab, char* smem)
{
    const int tid = threadIdx.x, lane = tid & 31, wid = tid >> 5;
    const int wm0 = (wid & 1) * 64, wn0 = (wid >> 1) * 32;
    const int rr = lane >> 2, cc = lane & 3;
    const int ntile = blockIdx.x, mtile = blockIdx.y;
    const long kbase = (long)slab * ktiles * BK;

    const int rowg = tid >> 3, sub = tid & 7;
    const int h7 = lane & 7;
    const int a_row = (lane & 15);
    const int a_hi = lane >> 4;
    const int b_rowoff = ((lane >> 4) << 3) + h7;
    const int b_hi = (lane >> 3) & 1;

    const float* asrc;
    float sA = 0.f, sBc = 0.f;
    if (MODE == 0) {
        asrc = A + (size_t)(mtile * BM + rowg) * D1 + kbase + sub * 8;
    } else {
        asrc = A + (size_t)(mtile * BM + rowg) * D1 + (kbase >> 2) + sub * 2;
        float xmin = decf(g_mm[2]), xmax = decf(g_mm[3]);
        sA = 2.0f / (xmax - xmin);
        sBc = -sA * xmin - 1.0f;
    }
    const float* wsrc = W + (size_t)(ntile * BN + rowg) * ldw + kbase + sub * 8;

    uint32_t soff[4];
#pragma unroll
    for (int g = 0; g < 4; g++) {
        int r = rowg + g * 32;
        soff[g] = r * 128 + ((sub ^ (r & 7)) << 4);
    }

    uint4 aS[4], bS[4];

    auto ldcvtB = [&](int kt) {
#pragma unroll
        for (int g = 0; g < 4; g++) {
            const float* p = wsrc + (size_t)g * 32 * ldw + (size_t)kt * BK;
            float4 w0 = *reinterpret_cast<const float4*>(p);
            float4 w1 = *reinterpret_cast<const float4*>(p + 4);
            bS[g] = make_uint4(pack2(w0.x, w0.y), pack2(w0.z, w0.w),
                               pack2(w1.x, w1.y), pack2(w1.z, w1.w));
        }
    };
    auto ldcvtA = [&](int kt) {
        if (MODE == 0) {
#pragma unroll
            for (int g = 0; g < 4; g++) {
                const float* p = asrc + (size_t)g * 32 * D1 + (size_t)kt * BK;
                float4 a0 = *reinterpret_cast<const float4*>(p);
                float4 a1 = *reinterpret_cast<const float4*>(p + 4);
                aS[g] = make_uint4(pack2(silu(a0.x), silu(a0.y)),
                                   pack2(silu(a0.z), silu(a0.w)),
                                   pack2(silu(a1.x), silu(a1.y)),
                                   pack2(silu(a1.z), silu(a1.w)));
            }
        } else {
#pragma unroll
            for (int g = 0; g < 4; g++) {
                float2 xv = *reinterpret_cast<const float2*>(
                    asrc + (size_t)g * 32 * D1 + kt * 16);
                float t0 = fmaf(xv.x, sA, sBc), t1 = fmaf(xv.y, sA, sBc);
                float q0 = t0 * t0, q1 = t1 * t1;
                aS[g] = make_uint4(
                    pack2(1.0f, t0),
                    pack2(fmaf(1.5f, q0, -0.5f), t0 * fmaf(2.5f, q0, -1.5f)),
                    pack2(1.0f, t1),
                    pack2(fmaf(1.5f, q1, -0.5f), t1 * fmaf(2.5f, q1, -1.5f)));
            }
        }
    };
    auto stA = [&](char* ast) {
#pragma unroll
        for (int g = 0; g < 4; g++) *reinterpret_cast<uint4*>(ast + soff[g]) = aS[g];
    };
    auto stB = [&](char* bst) {
#pragma unroll
        for (int g = 0; g < 4; g++) *reinterpret_cast<uint4*>(bst + soff[g]) = bS[g];
    };

    float acc[4][4][4] = {};

    auto compute = [&](const char* Ast, const char* Bst) {
        const uint32_t abase = (uint32_t)__cvta_generic_to_shared(Ast);
        const uint32_t bbase = (uint32_t)__cvta_generic_to_shared(Bst);
#pragma unroll
        for (int kc = 0; kc < 4; kc++) {
            unsigned af[4][4];
#pragma unroll
            for (int i = 0; i < 4; i++) {
                uint32_t addr = abase + (wm0 + i * 16 + a_row) * 128 +
                                (((2 * kc + a_hi) ^ h7) << 4);
                asm volatile(
                    "ldmatrix.sync.aligned.m8n8.x4.shared.b16 {%0,%1,%2,%3}, [%4];"
                    : "=r"(af[i][0]), "=r"(af[i][1]), "=r"(af[i][2]), "=r"(af[i][3])
                    : "r"(addr));
            }
            unsigned bfr[8];
#pragma unroll
            for (int jj = 0; jj < 2; jj++) {
                uint32_t addr = bbase + (wn0 + jj * 16 + b_rowoff) * 128 +
                                (((2 * kc + b_hi) ^ h7) << 4);
                asm volatile(
                    "ldmatrix.sync.aligned.m8n8.x4.shared.b16 {%0,%1,%2,%3}, [%4];"
                    : "=r"(bfr[jj * 4]), "=r"(bfr[jj * 4 + 1]),
                      "=r"(bfr[jj * 4 + 2]), "=r"(bfr[jj * 4 + 3])
                    : "r"(addr));
            }
#pragma unroll
            for (int j = 0; j < 4; j++) {
                unsigned b0 = bfr[(j >> 1) * 4 + (j & 1) * 2];
                unsigned b1 = bfr[(j >> 1) * 4 + (j & 1) * 2 + 1];
#pragma unroll
                for (int i = 0; i < 4; i++) {
                    asm volatile(
                        "mma.sync.aligned.m16n8k16.row.col.f32.f16.f16.f32 "
                        "{%0,%1,%2,%3}, {%4,%5,%6,%7}, {%8,%9}, {%0,%1,%2,%3};"
                        : "+f"(acc[i][j][0]), "+f"(acc[i][j][1]),
                          "+f"(acc[i][j][2]), "+f"(acc[i][j][3])
                        : "r"(af[i][0]), "r"(af[i][1]), "r"(af[i][2]), "r"(af[i][3]),
                          "r"(b0), "r"(b1));
                }
            }
        }
    };

    char* Abuf[2] = { smem, smem + TILE_BS };
    char* Bbuf[2] = { smem + 2 * TILE_BS, smem + 3 * TILE_BS };

    ldcvtA(0); ldcvtB(0);
    stA(Abuf[0]); stB(Bbuf[0]);
    __syncthreads();

    for (int kt = 0; kt < ktiles; kt++) {
        const int cur = kt & 1;
        const bool more = (kt + 1) < ktiles;
        compute(Abuf[cur], Bbuf[cur]);
        if (more) {
            ldcvtA(kt + 1); ldcvtB(kt + 1);
            stA(Abuf[cur ^ 1]); stB(Bbuf[cur ^ 1]);
        }
        __syncthreads();
    }

    const int c2 = cc * 2;
#pragma unroll
    for (int i = 0; i < 4; i++) {
        int row = mtile * BM + wm0 + i * 16 + rr;
#pragma unroll
        for (int j = 0; j < 4; j++) {
            int col = ntile * BN + wn0 + j * 8 + c2;
            size_t o = ((size_t)slab * B_SZ + row) * (size_t)D2 + col;
            *reinterpret_cast<float2*>(&Cp[o]) = make_float2(acc[i][j][0], acc[i][j][1]);
            *reinterpret_cast<float2*>(&Cp[o + 8 * (size_t)D2]) =
                make_float2(acc[i][j][2], acc[i][j][3]);
        }
    }
}

// merged layer-1: z<S3 base (2 kt), z>=S3 poly (4 kt); one wave of 48 CTAs
__global__ void __launch_bounds__(NT_BS, 2) kal_l1(
    const float* __restrict__ h0,
    const float* __restrict__ BW, const float* __restrict__ PW,
    float* __restrict__ Cp)
{
    extern __shared__ char smem[];
    const int z = blockIdx.z;
    if (z < S3)
        l1_body<0>(h0, BW, (long)D1, Cp, KT3, z, smem);
    else
        l1_body<1>(h0, PW, (long)D1 * 4, Cp + (size_t)S3 * B_SZ * D2, KT4, z - S3, smem);
}

// ===================== small kernels =====================
__global__ void k_init() {
    g_mm[0] = encf(FLT_MAX); g_mm[1] = encf(-FLT_MAX);
    g_mm[2] = encf(FLT_MAX); g_mm[3] = encf(-FLT_MAX);
}

__global__ void k_minmax(const float4* __restrict__ x, int n4) {
    float lo = FLT_MAX, hi = -FLT_MAX;
    for (int i = blockIdx.x * blockDim.x + threadIdx.x; i < n4; i += gridDim.x * blockDim.x) {
        float4 v = x[i];
        lo = fminf(lo, fminf(fminf(v.x, v.y), fminf(v.z, v.w)));
        hi = fmaxf(hi, fmaxf(fmaxf(v.x, v.y), fmaxf(v.z, v.w)));
    }
#pragma unroll
    for (int o = 16; o; o >>= 1) {
        lo = fminf(lo, __shfl_xor_sync(0xffffffffu, lo, o));
        hi = fmaxf(hi, __shfl_xor_sync(0xffffffffu, hi, o));
    }
    __shared__ float slo[8], shi[8];
    if ((threadIdx.x & 31) == 0) { slo[threadIdx.x >> 5] = lo; shi[threadIdx.x >> 5] = hi; }
    __syncthreads();
    if (threadIdx.x == 0) {
#pragma unroll
        for (int w = 1; w < 8; w++) { lo = fminf(lo, slo[w]); hi = fmaxf(hi, shi[w]); }
        atomicMin(&g_mm[0], encf(lo));
        atomicMax(&g_mm[1], encf(hi));
    }
}

__global__ void k_reduce_ln0(const float* __restrict__ part,
                             const float* __restrict__ gamma,
                             const float* __restrict__ beta) {
    const int b = blockIdx.x, tid = threadIdx.x;
    float2 hv = make_float2(0.f, 0.f);
    for (int s = 0; s < S0_TOT; s++) {
        float2 v = *reinterpret_cast<const float2*>(
            &part[((size_t)s * B_SZ + b) * D1 + tid * 2]);
        hv.x += v.x; hv.y += v.y;
    }
    __shared__ float sbuf[32];
    float mean = blkSum(hv.x + hv.y, sbuf) * (1.0f / D1);
    float dx = hv.x - mean, dy = hv.y - mean;
    float inv = rsqrtf(blkSum(dx * dx + dy * dy, sbuf) * (1.0f / D1) + 1e-5f);
    float2 gv = *reinterpret_cast<const float2*>(&gamma[tid * 2]);
    float2 bv = *reinterpret_cast<const float2*>(&beta[tid * 2]);
    float a0 = silu(dx * inv * gv.x + bv.x);
    float a1 = silu(dy * inv * gv.y + bv.y);
    *reinterpret_cast<float2*>(&g_h0[b * D1 + tid * 2]) = make_float2(a0, a1);
    float lo = fminf(a0, a1), hi = fmaxf(a0, a1);
#pragma unroll
    for (int o = 16; o; o >>= 1) {
        lo = fminf(lo, __shfl_xor_sync(0xffffffffu, lo, o));
        hi = fmaxf(hi, __shfl_xor_sync(0xffffffffu, hi, o));
    }
    __shared__ float slo[16], shi[16];
    if ((tid & 31) == 0) { slo[tid >> 5] = lo; shi[tid >> 5] = hi; }
    __syncthreads();
    if (tid == 0) {
#pragma unroll
        for (int w = 1; w < 16; w++) { lo = fminf(lo, slo[w]); hi = fmaxf(hi, shi[w]); }
        atomicMin(&g_mm[2], encf(lo));
        atomicMax(&g_mm[3], encf(hi));
    }
}

__global__ void k_reduce_ln1(const float* __restrict__ part,
                             const float* __restrict__ gamma,
                             const float* __restrict__ beta,
                             const float* __restrict__ ow,
                             const float* __restrict__ ob,
                             float* __restrict__ out) {
    const int b = blockIdx.x, tid = threadIdx.x;
    float acc = 0.f;
    for (int s = 0; s < SL1_TOT; s++) acc += part[((size_t)s * B_SZ + b) * D2 + tid];
    __shared__ float sbuf[32];
    float mean = blkSum(acc, sbuf) * (1.0f / D2);
    float d = acc - mean;
    float var = blkSum(d * d, sbuf) * (1.0f / D2);
    float y = d * rsqrtf(var + 1e-5f) * gamma[tid] + beta[tid];
    float a = silu(y);
    float l0 = blkSum(a * ow[tid], sbuf);
    float l1 = blkSum(a * ow[128 + tid], sbuf);
    if (tid == 0) {
        l0 += ob[0]; l1 += ob[1];
        float m = fmaxf(l0, l1);
        float e0 = expf(l0 - m), e1 = expf(l1 - m);
        float inv = 1.f / (e0 + e1);
        out[b * 2 + 0] = e0 * inv;
        out[b * 2 + 1] = e1 * inv;
    }
}

extern "C" void kernel_launch(void* const* d_in, const int* in_sizes, int n_in,
                              void* d_out, int out_size) {
    (void)in_sizes; (void)n_in; (void)out_size;
    const float* x       = (const float*)d_in[0];
    const float* base_w0 = (const float*)d_in[1];
    const float* poly_w0 = (const float*)d_in[2];
    const float* ln_g0   = (const float*)d_in[3];
    const float* ln_b0   = (const float*)d_in[4];
    const float* base_w1 = (const float*)d_in[5];
    const float* poly_w1 = (const float*)d_in[6];
    const float* ln_g1   = (const float*)d_in[7];
    const float* ln_b1   = (const float*)d_in[8];
    const float* out_w   = (const float*)d_in[9];
    const float* out_b   = (const float*)d_in[10];
    float* out = (float*)d_out;

    float *part0, *part1, *h0;
    cudaGetSymbolAddress((void**)&part0, g_part0);
    cudaGetSymbolAddress((void**)&part1, g_part1);
    cudaGetSymbolAddress((void**)&h0, g_h0);

    cudaFuncSetAttribute(kal_l0, cudaFuncAttributeMaxDynamicSharedMemorySize, SMEM_WS);
    cudaFuncSetAttribute(kal_l1, cudaFuncAttributeMaxDynamicSharedMemorySize, SMEM_BS);

    k_init<<<1, 1>>>();
    k_minmax<<<2048, 256>>>((const float4*)x, B_SZ * D0 / 4);

    kal_l0<<<dim3(8, 2, S0_TOT), NT_WS, SMEM_WS>>>(x, base_w0, poly_w0, part0);
    k_reduce_ln0<<<B_SZ, 512>>>(part0, ln_g0, ln_b0);

    kal_l1<<<dim3(1, 2, SL1_TOT), NT_BS, SMEM_BS>>>(h0, base_w1, poly_w1, part1);
    k_reduce_ln1<<<B_SZ, 128>>>(part1, ln_g1, ln_b1, out_w, out_b, out);
}